// round 7
// baseline (speedup 1.0000x reference)
#include <cuda_runtime.h>
#include <cstdint>

typedef unsigned long long ull;

#define B_      2
#define L_      4096
#define HIDDEN  512
#define HEADS   8
#define HD      64
#define PREFIX  1
#define M_ROWS  (B_ * L_)        // 8192

// ---- bf16 hi/lo split storage (allocation-free: __device__ globals) ----
__device__ __align__(16) uint16_t gx_hi[M_ROWS * HIDDEN],  gx_lo[M_ROWS * HIDDEN];
__device__ __align__(16) uint16_t gwi_hi[3 * HIDDEN * HIDDEN], gwi_lo[3 * HIDDEN * HIDDEN];
__device__ __align__(16) uint16_t gwo_hi[HIDDEN * HIDDEN], gwo_lo[HIDDEN * HIDDEN];
__device__ __align__(16) uint16_t gq_hi[M_ROWS * HIDDEN],  gq_lo[M_ROWS * HIDDEN];
__device__ __align__(16) uint16_t gk_hi[M_ROWS * HIDDEN],  gk_lo[M_ROWS * HIDDEN];
__device__ __align__(16) uint16_t gv_hi[M_ROWS * HIDDEN],  gv_lo[M_ROWS * HIDDEN];
__device__ __align__(16) uint16_t gctx_hi[M_ROWS * HIDDEN], gctx_lo[M_ROWS * HIDDEN];

// ============================================================
// helpers
// ============================================================
__device__ __forceinline__ uint32_t smem_u32(const void* p) {
    uint32_t a;
    asm("{ .reg .u64 t; cvta.to.shared.u64 t, %1; cvt.u32.u64 %0, t; }" : "=r"(a) : "l"(p));
    return a;
}
__device__ __forceinline__ uint32_t f2u(float x) { return __float_as_uint(x); }
__device__ __forceinline__ uint32_t prmt_hi16(uint32_t a, uint32_t b) {
    uint32_t r; asm("prmt.b32 %0,%1,%2,0x7632;" : "=r"(r) : "r"(a), "r"(b)); return r;
}
__device__ __forceinline__ uint32_t cvt_bf16x2(float lo, float hi) {
    uint32_t r; asm("cvt.rn.bf16x2.f32 %0,%1,%2;" : "=r"(r) : "f"(hi), "f"(lo)); return r;
}
__device__ __forceinline__ uint16_t bf16_rn(float x) {
    uint16_t u; asm("cvt.rn.bf16.f32 %0,%1;" : "=h"(u) : "f"(x)); return u;
}
__device__ __forceinline__ float ex2f(float x) {
    float r; asm("ex2.approx.f32 %0,%1;" : "=f"(r) : "f"(x)); return r;
}
__device__ __forceinline__ uint32_t swz128(uint32_t o) { return o ^ ((o >> 3) & 0x70u); }

__device__ __forceinline__ void cp16(uint32_t dst, const void* src) {
    asm volatile("cp.async.cg.shared.global [%0], [%1], 16;" :: "r"(dst), "l"(src) : "memory");
}
__device__ __forceinline__ void cp_commit() {
    asm volatile("cp.async.commit_group;" ::: "memory");
}
template <int N> __device__ __forceinline__ void cp_wait() {
    asm volatile("cp.async.wait_group %0;" :: "n"(N) : "memory");
}

__device__ __forceinline__ void ldsm4(uint32_t& r0, uint32_t& r1, uint32_t& r2, uint32_t& r3,
                                      uint32_t addr) {
    asm volatile("ldmatrix.sync.aligned.m8n8.x4.shared.b16 {%0,%1,%2,%3}, [%4];"
                 : "=r"(r0), "=r"(r1), "=r"(r2), "=r"(r3) : "r"(addr));
}
__device__ __forceinline__ void ldsm4t(uint32_t& r0, uint32_t& r1, uint32_t& r2, uint32_t& r3,
                                       uint32_t addr) {
    asm volatile("ldmatrix.sync.aligned.m8n8.x4.trans.shared.b16 {%0,%1,%2,%3}, [%4];"
                 : "=r"(r0), "=r"(r1), "=r"(r2), "=r"(r3) : "r"(addr));
}
__device__ __forceinline__ void mma_bf16(float* c, const uint32_t* a, uint32_t b0, uint32_t b1) {
    asm volatile(
        "mma.sync.aligned.m16n8k16.row.col.f32.bf16.bf16.f32 "
        "{%0,%1,%2,%3},{%4,%5,%6,%7},{%8,%9},{%0,%1,%2,%3};"
        : "+f"(c[0]), "+f"(c[1]), "+f"(c[2]), "+f"(c[3])
        : "r"(a[0]), "r"(a[1]), "r"(a[2]), "r"(a[3]), "r"(b0), "r"(b1));
}

// ============================================================
// conversion kernels: fp32 -> bf16 hi/lo split
// ============================================================
__global__ __launch_bounds__(256) void conv_x_kernel(const float* __restrict__ x)
{
    size_t gid = (size_t)blockIdx.x * 256 + threadIdx.x;
    size_t i = gid * 4;
    float4 v = *(const float4*)(x + i);
    uint32_t bx = f2u(v.x), by = f2u(v.y), bz = f2u(v.z), bw = f2u(v.w);
    uint2 H, Lw;
    H.x = prmt_hi16(bx, by);
    H.y = prmt_hi16(bz, bw);
    Lw.x = cvt_bf16x2(v.x - __uint_as_float(bx & 0xffff0000u),
                      v.y - __uint_as_float(by & 0xffff0000u));
    Lw.y = cvt_bf16x2(v.z - __uint_as_float(bz & 0xffff0000u),
                      v.w - __uint_as_float(bw & 0xffff0000u));
    *(uint2*)(gx_hi + i) = H;
    *(uint2*)(gx_lo + i) = Lw;
}

__global__ __launch_bounds__(256) void conv_wT_kernel(const float* __restrict__ w,
                                                      int K, int N, int which)
{
    __shared__ float t[32][33];
    uint16_t* dh = which ? gwo_hi : gwi_hi;
    uint16_t* dl = which ? gwo_lo : gwi_lo;
    int n0 = blockIdx.x * 32, k0 = blockIdx.y * 32;
    int tx = threadIdx.x & 31, ty = threadIdx.x >> 5;
#pragma unroll
    for (int i = 0; i < 4; i++)
        t[ty + 8 * i][tx] = w[(size_t)(k0 + ty + 8 * i) * N + n0 + tx];
    __syncthreads();
#pragma unroll
    for (int i = 0; i < 4; i++) {
        int nn = ty + 8 * i;
        float v = t[tx][nn];
        uint32_t b = f2u(v);
        size_t idx = (size_t)(n0 + nn) * K + k0 + tx;
        dh[idx] = (uint16_t)(b >> 16);
        dl[idx] = bf16_rn(v - __uint_as_float(b & 0xffff0000u));
    }
}

// ============================================================
// GEMM bf16x3 via mma.sync + cp.async 2-stage pipeline.
// Interleaved MMA passes: reuse distance per accumulator >= 8.
// ============================================================
template <int MODE>
__global__ __launch_bounds__(256, 1) void gemm_bf16_kernel(
    const float* __restrict__ bias, float* __restrict__ Cout)
{
    extern __shared__ char smp[];
    const uint32_t sbase = smem_u32(smp);
    int tid = threadIdx.x;
    int lane = tid & 31, w = tid >> 5;
    int wm = w & 1, wn = w >> 1;
    int bm = blockIdx.y, bn = blockIdx.x;

    const uint16_t* Ahi = (MODE == 0) ? gx_hi : gctx_hi;
    const uint16_t* Alo = (MODE == 0) ? gx_lo : gctx_lo;
    const uint16_t* Bhi = (MODE == 0) ? gwi_hi : gwo_hi;
    const uint16_t* Blo = (MODE == 0) ? gwi_lo : gwo_lo;

    int r = tid >> 1, g0 = (tid & 1) * 4;
    size_t aoff = (size_t)(bm * 128 + r) * HIDDEN;
    size_t boff = (size_t)(bn * 128 + r) * HIDDEN;

    float acc[4][4][4];
#pragma unroll
    for (int i = 0; i < 4; i++)
#pragma unroll
        for (int j = 0; j < 4; j++)
#pragma unroll
            for (int e = 0; e < 4; e++) acc[i][j][e] = 0.f;

#define ISSUE_CHUNK(kc, buf) do {                                              \
        uint32_t dst = sbase + (uint32_t)(buf) * 65536u;                        \
        const uint16_t* ah = Ahi + aoff + (kc) * 64;                            \
        const uint16_t* al = Alo + aoff + (kc) * 64;                            \
        const uint16_t* bh = Bhi + boff + (kc) * 64;                            \
        const uint16_t* bl = Blo + boff + (kc) * 64;                            \
        _Pragma("unroll")                                                       \
        for (int i = 0; i < 4; i++) {                                           \
            uint32_t so = swz128((uint32_t)r * 128u + (uint32_t)(g0 + i) * 16u);\
            cp16(dst + so,           ah + (g0 + i) * 8);                        \
            cp16(dst + 16384u + so,  al + (g0 + i) * 8);                        \
            cp16(dst + 32768u + so,  bh + (g0 + i) * 8);                        \
            cp16(dst + 49152u + so,  bl + (g0 + i) * 8);                        \
        }                                                                       \
        cp_commit();                                                            \
    } while (0)

    ISSUE_CHUNK(0, 0);

    const int NK = HIDDEN / 64;   // 8
    for (int kc = 0; kc < NK; kc++) {
        if (kc + 1 < NK) {
            ISSUE_CHUNK(kc + 1, (kc + 1) & 1);
            cp_wait<1>();
        } else {
            cp_wait<0>();
        }
        __syncthreads();

        uint32_t abase = sbase + (uint32_t)(kc & 1) * 65536u;
        uint32_t bbase = abase + 32768u;
#pragma unroll
        for (int ks = 0; ks < 4; ks++) {
            uint32_t ah[4][4], al[4][4];
#pragma unroll
            for (int mi = 0; mi < 4; mi++) {
                uint32_t off = swz128((uint32_t)(wm * 64 + mi * 16 + (lane & 15)) * 128u
                                      + (uint32_t)(ks * 32 + ((lane & 16) ? 16 : 0)));
                ldsm4(ah[mi][0], ah[mi][1], ah[mi][2], ah[mi][3], abase + off);
                ldsm4(al[mi][0], al[mi][1], al[mi][2], al[mi][3], abase + 16384u + off);
            }
            uint32_t bh[2][4], bl[2][4];
#pragma unroll
            for (int np = 0; np < 2; np++) {
                uint32_t boffs = swz128((uint32_t)(wn * 32 + np * 16 + (lane & 7)
                                                   + ((lane & 16) ? 8 : 0)) * 128u
                                        + (uint32_t)(ks * 32 + ((lane & 8) ? 16 : 0)));
                ldsm4(bh[np][0], bh[np][1], bh[np][2], bh[np][3], bbase + boffs);
                ldsm4(bl[np][0], bl[np][1], bl[np][2], bl[np][3], bbase + 16384u + boffs);
            }
            // interleaved passes: 4 independent accumulators per pass
#pragma unroll
            for (int np = 0; np < 2; np++) {
#pragma unroll
                for (int mi = 0; mi < 4; mi++)
                    mma_bf16(acc[mi][2 * np],     ah[mi], bh[np][0], bh[np][1]);
#pragma unroll
                for (int mi = 0; mi < 4; mi++)
                    mma_bf16(acc[mi][2 * np + 1], ah[mi], bh[np][2], bh[np][3]);
#pragma unroll
                for (int mi = 0; mi < 4; mi++)
                    mma_bf16(acc[mi][2 * np],     ah[mi], bl[np][0], bl[np][1]);
#pragma unroll
                for (int mi = 0; mi < 4; mi++)
                    mma_bf16(acc[mi][2 * np + 1], ah[mi], bl[np][2], bl[np][3]);
#pragma unroll
                for (int mi = 0; mi < 4; mi++)
                    mma_bf16(acc[mi][2 * np],     al[mi], bh[np][0], bh[np][1]);
#pragma unroll
                for (int mi = 0; mi < 4; mi++)
                    mma_bf16(acc[mi][2 * np + 1], al[mi], bh[np][2], bh[np][3]);
            }
        }
        __syncthreads();
    }
#undef ISSUE_CHUNK

    // ---- epilogue ----
#pragma unroll
    for (int mi = 0; mi < 4; mi++) {
        int r0 = bm * 128 + wm * 64 + mi * 16 + (lane >> 2);
#pragma unroll
        for (int nj = 0; nj < 4; nj++) {
            int c0 = bn * 128 + wn * 32 + nj * 8 + 2 * (lane & 3);
            float bb0 = __ldg(bias + c0), bb1 = __ldg(bias + c0 + 1);
            float v0 = acc[mi][nj][0] + bb0, v1 = acc[mi][nj][1] + bb1;
            float v2 = acc[mi][nj][2] + bb0, v3 = acc[mi][nj][3] + bb1;
            if (MODE == 0) {
                int which = c0 >> 9, h = (c0 >> 6) & 7, d = c0 & 63;
                uint16_t* dh = (which == 0) ? gq_hi : (which == 1) ? gk_hi : gv_hi;
                uint16_t* dl = (which == 0) ? gq_lo : (which == 1) ? gk_lo : gv_lo;
                int b = r0 >> 12;
                size_t base0 = ((size_t)((b * 8 + h) * L_ + (r0 & 4095))) * 64 + d;
                size_t base1 = base0 + 8 * 64;
                uint32_t u0 = f2u(v0), u1 = f2u(v1), u2 = f2u(v2), u3 = f2u(v3);
                *(uint32_t*)(dh + base0) = prmt_hi16(u0, u1);
                *(uint32_t*)(dl + base0) =
                    cvt_bf16x2(v0 - __uint_as_float(u0 & 0xffff0000u),
                               v1 - __uint_as_float(u1 & 0xffff0000u));
                *(uint32_t*)(dh + base1) = prmt_hi16(u2, u3);
                *(uint32_t*)(dl + base1) =
                    cvt_bf16x2(v2 - __uint_as_float(u2 & 0xffff0000u),
                               v3 - __uint_as_float(u3 & 0xffff0000u));
            } else {
                *(float2*)(Cout + (size_t)r0 * HIDDEN + c0) = make_float2(v0, v1);
                *(float2*)(Cout + (size_t)(r0 + 8) * HIDDEN + c0) = make_float2(v2, v3);
            }
        }
    }
}

// ============================================================
// Attention SMEM: Q 32KB; K/V double buffer (2 x 32KB). 96KB.
// ============================================================
#define SQHI 0u
#define SQLO 16384u
#define SKV0 32768u
#define ATTN_SMEM 98304

__global__ __launch_bounds__(256, 1) void attn_mma_kernel()
{
    extern __shared__ char smp[];
    const uint32_t sbase = smem_u32(smp);
    int tid = threadIdx.x;
    int w = tid >> 5, lane = tid & 31;

    int bh = blockIdx.x;                            // b*8 + h
    int qt = (int)gridDim.y - 1 - (int)blockIdx.y;  // heavy tiles first
    int nkt = 2 * qt + 2;                           // 64-key tiles

    int ct = tid & 127;
    int rr = ct >> 1, g0 = (ct & 1) * 4;
    const uint16_t* srch = (tid < 128) ? gk_hi : gv_hi;
    const uint16_t* srcl = (tid < 128) ? gk_lo : gv_lo;
    uint32_t dsel = (tid < 128) ? 0u : 16384u;

#define ISSUE_KV(kt, buf) do {                                                   \
        uint32_t dst = sbase + SKV0 + (uint32_t)(buf) * 32768u + dsel;           \
        const uint16_t* sh = srch + ((size_t)bh * L_ + (size_t)(kt) * 64 + rr) * 64; \
        const uint16_t* sl = srcl + ((size_t)bh * L_ + (size_t)(kt) * 64 + rr) * 64; \
        _Pragma("unroll")                                                        \
        for (int i = 0; i < 4; i++) {                                            \
            uint32_t so = swz128((uint32_t)rr * 128u + (uint32_t)(g0 + i) * 16u);\
            cp16(dst + so,          sh + (g0 + i) * 8);                          \
            cp16(dst + 8192u + so,  sl + (g0 + i) * 8);                          \
        }                                                                        \
        cp_commit();                                                             \
    } while (0)

    // Prologue: Q tile copy + first K/V issue
    {
        const uint4* qh4 = (const uint4*)(gq_hi + ((size_t)bh * L_ + (size_t)qt * 128 + (tid >> 1)) * 64);
        const uint4* ql4 = (const uint4*)(gq_lo + ((size_t)bh * L_ + (size_t)qt * 128 + (tid >> 1)) * 64);
        int qg0 = (tid & 1) * 4;
#pragma unroll
        for (int i = 0; i < 4; i++) {
            uint32_t so = swz128((uint32_t)(tid >> 1) * 128u + (uint32_t)(qg0 + i) * 16u);
            *(uint4*)(smp + SQHI + so) = qh4[qg0 + i];
            *(uint4*)(smp + SQLO + so) = ql4[qg0 + i];
        }
    }
    ISSUE_KV(0, 0);
    __syncthreads();

    uint32_t qh[4][4], ql[4][4];
    {
        int arow = 16 * w + (lane & 15);
#pragma unroll
        for (int ks = 0; ks < 4; ks++) {
            uint32_t off = swz128((uint32_t)arow * 128u
                                  + (uint32_t)(ks * 32 + ((lane & 16) ? 16 : 0)));
            ldsm4(qh[ks][0], qh[ks][1], qh[ks][2], qh[ks][3], sbase + SQHI + off);
            ldsm4(ql[ks][0], ql[ks][1], ql[ks][2], ql[ks][3], sbase + SQLO + off);
        }
    }

    float oc[8][4];
#pragma unroll
    for (int n = 0; n < 8; n++)
#pragma unroll
        for (int j = 0; j < 4; j++) oc[n][j] = 0.f;
    float lsum0 = 0.f, lsum1 = 0.f;

    const float Cc = 0.18033688011112042f;  // (1/8) * log2(e)
    int row0 = qt * 128 + 16 * w + (lane >> 2);
    int row1 = row0 + 8;

    for (int kt = 0; kt < nkt; ++kt) {
        if (kt + 1 < nkt) {
            ISSUE_KV(kt + 1, (kt + 1) & 1);
            cp_wait<1>();
        } else {
            cp_wait<0>();
        }
        __syncthreads();

        uint32_t kvb = sbase + SKV0 + (uint32_t)(kt & 1) * 32768u;

        // ---- S = Q K^T : interleaved passes over np-pairs ----
        float sc[8][4];
#pragma unroll
        for (int n = 0; n < 8; n++)
#pragma unroll
            for (int j = 0; j < 4; j++) sc[n][j] = 0.f;

#pragma unroll
        for (int ks = 0; ks < 4; ks++) {
#pragma unroll
            for (int npp = 0; npp < 2; npp++) {
                int key0 = (2 * npp) * 16 + (lane & 7) + ((lane & 16) ? 8 : 0);
                uint32_t col = (uint32_t)(ks * 32 + ((lane & 8) ? 16 : 0));
                uint32_t off0 = swz128((uint32_t)key0 * 128u + col);
                uint32_t off1 = swz128((uint32_t)(key0 + 16) * 128u + col);
                uint32_t h00, h01, h02, h03, l00, l01, l02, l03;
                uint32_t h10, h11, h12, h13, l10, l11, l12, l13;
                ldsm4(h00, h01, h02, h03, kvb + off0);
                ldsm4(l00, l01, l02, l03, kvb + 8192u + off0);
                ldsm4(h10, h11, h12, h13, kvb + off1);
                ldsm4(l10, l11, l12, l13, kvb + 8192u + off1);
                float* s0 = sc[4 * npp + 0];
                float* s1 = sc[4 * npp + 1];
                float* s2 = sc[4 * npp + 2];
                float* s3 = sc[4 * npp + 3];
                mma_bf16(s0, qh[ks], h00, h01);
                mma_bf16(s1, qh[ks], h02, h03);
                mma_bf16(s2, qh[ks], h10, h11);
                mma_bf16(s3, qh[ks], h12, h13);
                mma_bf16(s0, qh[ks], l00, l01);
                mma_bf16(s1, qh[ks], l02, l03);
                mma_bf16(s2, qh[ks], l10, l11);
                mma_bf16(s3, qh[ks], l12, l13);
                mma_bf16(s0, ql[ks], h00, h01);
                mma_bf16(s1, ql[ks], h02, h03);
                mma_bf16(s2, ql[ks], h10, h11);
                mma_bf16(s3, ql[ks], h12, h13);
            }
        }

        // ---- softmax (unnormalized) ----
        bool edge = (kt == 0) || (kt >= 2 * qt);
        int colb = kt * 64 + 2 * (lane & 3);
#pragma unroll
        for (int n = 0; n < 8; n++) {
            float e0 = ex2f(sc[n][0] * Cc);
            float e1 = ex2f(sc[n][1] * Cc);
            float e2 = ex2f(sc[n][2] * Cc);
            float e3 = ex2f(sc[n][3] * Cc);
            if (edge) {
                int c0 = colb + 8 * n, c1 = c0 + 1;
                bool k00 = (c0 <= row0) && (c0 >= PREFIX || row0 < PREFIX);
                bool k01 = (c1 <= row0) && (c1 >= PREFIX || row0 < PREFIX);
                bool k10 = (c0 <= row1) && (c0 >= PREFIX || row1 < PREFIX);
                bool k11 = (c1 <= row1) && (c1 >= PREFIX || row1 < PREFIX);
                e0 = k00 ? e0 : 0.f;
                e1 = k01 ? e1 : 0.f;
                e2 = k10 ? e2 : 0.f;
                e3 = k11 ? e3 : 0.f;
            }
            sc[n][0] = e0; sc[n][1] = e1; sc[n][2] = e2; sc[n][3] = e3;
            lsum0 += e0 + e1;
            lsum1 += e2 + e3;
        }

        // ---- O += P V : interleaved passes over dp-pairs ----
#pragma unroll
        for (int t = 0; t < 4; t++) {
            uint32_t ph[4], pl[4];
            {
                float* cA = sc[2 * t];
                float* cB = sc[2 * t + 1];
                uint32_t a0 = f2u(cA[0]), a1 = f2u(cA[1]);
                uint32_t a2 = f2u(cA[2]), a3 = f2u(cA[3]);
                uint32_t b0 = f2u(cB[0]), b1 = f2u(cB[1]);
                uint32_t b2 = f2u(cB[2]), b3 = f2u(cB[3]);
                ph[0] = prmt_hi16(a0, a1);
                ph[1] = prmt_hi16(a2, a3);
                ph[2] = prmt_hi16(b0, b1);
                ph[3] = prmt_hi16(b2, b3);
                pl[0] = cvt_bf16x2(cA[0] - __uint_as_float(a0 & 0xffff0000u),
                                   cA[1] - __uint_as_float(a1 & 0xffff0000u));
                pl[1] = cvt_bf16x2(cA[2] - __uint_as_float(a2 & 0xffff0000u),
                                   cA[3] - __uint_as_float(a3 & 0xffff0000u));
                pl[2] = cvt_bf16x2(cB[0] - __uint_as_float(b0 & 0xffff0000u),
                                   cB[1] - __uint_as_float(b1 & 0xffff0000u));
                pl[3] = cvt_bf16x2(cB[2] - __uint_as_float(b2 & 0xffff0000u),
                                   cB[3] - __uint_as_float(b3 & 0xffff0000u));
            }
            int key = t * 16 + (lane & 7) + ((lane & 8) ? 8 : 0);
#pragma unroll
            for (int dpp = 0; dpp < 2; dpp++) {
                uint32_t col0 = (uint32_t)((2 * dpp) * 32 + ((lane & 16) ? 16 : 0));
                uint32_t off0 = swz128((uint32_t)key * 128u + col0);
                uint32_t off1 = swz128((uint32_t)key * 128u + col0 + 32u);
                uint32_t h00, h01, h02, h03, l00, l01, l02, l03;
                uint32_t h10, h11, h12, h13, l10, l11, l12, l13;
                ldsm4t(h00, h01, h02, h03, kvb + 16384u + off0);
                ldsm4t(l00, l01, l02, l03, kvb + 24576u + off0);
                ldsm4t(h10, h11, h12, h13, kvb + 16384u + off1);
                ldsm4t(l10, l11, l12, l13, kvb + 24576u + off1);
                float* o0 = oc[4 * dpp + 0];
                float* o1 = oc[4 * dpp + 1];
                float* o2 = oc[4 * dpp + 2];
                float* o3 = oc[4 * dpp + 3];
                mma_bf16(o0, ph, h00, h01);
                mma_bf16(o1, ph, h02, h03);
                mma_bf16(o2, ph, h10, h11);
                mma_bf16(o3, ph, h12, h13);
                mma_bf16(o0, ph, l00, l01);
                mma_bf16(o1, ph, l02, l03);
                mma_bf16(o2, ph, l10, l11);
                mma_bf16(o3, ph, l12, l13);
                mma_bf16(o0, pl, h00, h01);
                mma_bf16(o1, pl, h02, h03);
                mma_bf16(o2, pl, h10, h11);
                mma_bf16(o3, pl, h12, h13);
            }
        }
        __syncthreads();
    }
#undef ISSUE_KV

    // lane reduction of lsum
    lsum0 += __shfl_xor_sync(0xffffffffu, lsum0, 1);
    lsum0 += __shfl_xor_sync(0xffffffffu, lsum0, 2);
    lsum1 += __shfl_xor_sync(0xffffffffu, lsum1, 1);
    lsum1 += __shfl_xor_sync(0xffffffffu, lsum1, 2);
    float inv0 = 1.f / lsum0, inv1 = 1.f / lsum1;

    // store ctx as bf16 hi/lo
    int b = bh >> 3, h = bh & 7;
    size_t r0base = (size_t)(b * L_ + row0) * HIDDEN + h * 64;
    size_t r1base = (size_t)(b * L_ + row1) * HIDDEN + h * 64;
#pragma unroll
    for (int n = 0; n < 8; n++) {
        int d = 8 * n + 2 * (lane & 3);
        float v0 = oc[n][0] * inv0, v1 = oc[n][1] * inv0;
        float v2 = oc[n][2] * inv1, v3 = oc[n][3] * inv1;
        uint32_t u0 = f2u(v0), u1 = f2u(v1), u2 = f2u(v2), u3 = f2u(v3);
        *(uint32_t*)(gctx_hi + r0base + d) = prmt_hi16(u0, u1);
        *(uint32_t*)(gctx_lo + r0base + d) =
            cvt_bf16x2(v0 - __uint_as_float(u0 & 0xffff0000u),
                       v1 - __uint_as_float(u1 & 0xffff0000u));
        *(uint32_t*)(gctx_hi + r1base + d) = prmt_hi16(u2, u3);
        *(uint32_t*)(gctx_lo + r1base + d) =
            cvt_bf16x2(v2 - __uint_as_float(u2 & 0xffff0000u),
                       v3 - __uint_as_float(u3 & 0xffff0000u));
    }
}

// ============================================================
extern "C" void kernel_launch(void* const* d_in, const int* in_sizes, int n_in,
                              void* d_out, int out_size)
{
    const float* x     = (const float*)d_in[0];
    const float* w_in  = (const float*)d_in[1];
    const float* b_in  = (const float*)d_in[2];
    const float* w_out = (const float*)d_in[3];
    const float* b_out = (const float*)d_in[4];
    float* out = (float*)d_out;

    conv_x_kernel<<<(M_ROWS * HIDDEN / 4) / 256, 256>>>(x);
    conv_wT_kernel<<<dim3(3 * HIDDEN / 32, HIDDEN / 32), 256>>>(w_in, HIDDEN, 3 * HIDDEN, 0);
    conv_wT_kernel<<<dim3(HIDDEN / 32, HIDDEN / 32), 256>>>(w_out, HIDDEN, HIDDEN, 1);

    cudaFuncSetAttribute(gemm_bf16_kernel<0>,
                         cudaFuncAttributeMaxDynamicSharedMemorySize, 131072);
    gemm_bf16_kernel<0><<<dim3(12, 64), 256, 131072>>>(b_in, nullptr);

    cudaFuncSetAttribute(attn_mma_kernel,
                         cudaFuncAttributeMaxDynamicSharedMemorySize, ATTN_SMEM);
    attn_mma_kernel<<<dim3(16, 32), 256, ATTN_SMEM>>>();

    cudaFuncSetAttribute(gemm_bf16_kernel<1>,
                         cudaFuncAttributeMaxDynamicSharedMemorySize, 131072);
    gemm_bf16_kernel<1><<<dim3(4, 64), 256, 131072>>>(b_out, out);
}

// round 8
// speedup vs baseline: 1.0847x; 1.0847x over previous
#include <cuda_runtime.h>
#include <cstdint>

typedef unsigned long long ull;

#define B_      2
#define L_      4096
#define HIDDEN  512
#define HEADS   8
#define HD      64
#define PREFIX  1
#define M_ROWS  (B_ * L_)        // 8192

// ---- bf16 hi/lo split storage (allocation-free: __device__ globals) ----
__device__ __align__(16) uint16_t gx_hi[M_ROWS * HIDDEN],  gx_lo[M_ROWS * HIDDEN];
__device__ __align__(16) uint16_t gwi_hi[3 * HIDDEN * HIDDEN], gwi_lo[3 * HIDDEN * HIDDEN];
__device__ __align__(16) uint16_t gwo_hi[HIDDEN * HIDDEN], gwo_lo[HIDDEN * HIDDEN];
__device__ __align__(16) uint16_t gq_hi[M_ROWS * HIDDEN],  gq_lo[M_ROWS * HIDDEN];
__device__ __align__(16) uint16_t gk_hi[M_ROWS * HIDDEN],  gk_lo[M_ROWS * HIDDEN];
__device__ __align__(16) uint16_t gv_hi[M_ROWS * HIDDEN],  gv_lo[M_ROWS * HIDDEN];
__device__ __align__(16) uint16_t gctx_hi[M_ROWS * HIDDEN], gctx_lo[M_ROWS * HIDDEN];

// ============================================================
// helpers
// ============================================================
__device__ __forceinline__ uint32_t smem_u32(const void* p) {
    uint32_t a;
    asm("{ .reg .u64 t; cvta.to.shared.u64 t, %1; cvt.u32.u64 %0, t; }" : "=r"(a) : "l"(p));
    return a;
}
__device__ __forceinline__ uint32_t f2u(float x) { return __float_as_uint(x); }
__device__ __forceinline__ uint32_t prmt_hi16(uint32_t a, uint32_t b) {
    uint32_t r; asm("prmt.b32 %0,%1,%2,0x7632;" : "=r"(r) : "r"(a), "r"(b)); return r;
}
__device__ __forceinline__ uint32_t cvt_bf16x2(float lo, float hi) {
    uint32_t r; asm("cvt.rn.bf16x2.f32 %0,%1,%2;" : "=r"(r) : "f"(hi), "f"(lo)); return r;
}
__device__ __forceinline__ uint16_t bf16_rn(float x) {
    uint16_t u; asm("cvt.rn.bf16.f32 %0,%1;" : "=h"(u) : "f"(x)); return u;
}
__device__ __forceinline__ float ex2f(float x) {
    float r; asm("ex2.approx.f32 %0,%1;" : "=f"(r) : "f"(x)); return r;
}
__device__ __forceinline__ uint32_t swz128(uint32_t o) { return o ^ ((o >> 3) & 0x70u); }

__device__ __forceinline__ void cp16(uint32_t dst, const void* src) {
    asm volatile("cp.async.cg.shared.global [%0], [%1], 16;" :: "r"(dst), "l"(src) : "memory");
}
__device__ __forceinline__ void cp_commit() {
    asm volatile("cp.async.commit_group;" ::: "memory");
}
template <int N> __device__ __forceinline__ void cp_wait() {
    asm volatile("cp.async.wait_group %0;" :: "n"(N) : "memory");
}

__device__ __forceinline__ void ldsm4(uint32_t& r0, uint32_t& r1, uint32_t& r2, uint32_t& r3,
                                      uint32_t addr) {
    asm volatile("ldmatrix.sync.aligned.m8n8.x4.shared.b16 {%0,%1,%2,%3}, [%4];"
                 : "=r"(r0), "=r"(r1), "=r"(r2), "=r"(r3) : "r"(addr));
}
__device__ __forceinline__ void ldsm4t(uint32_t& r0, uint32_t& r1, uint32_t& r2, uint32_t& r3,
                                       uint32_t addr) {
    asm volatile("ldmatrix.sync.aligned.m8n8.x4.trans.shared.b16 {%0,%1,%2,%3}, [%4];"
                 : "=r"(r0), "=r"(r1), "=r"(r2), "=r"(r3) : "r"(addr));
}
__device__ __forceinline__ void mma_bf16(float* c, const uint32_t* a, uint32_t b0, uint32_t b1) {
    asm volatile(
        "mma.sync.aligned.m16n8k16.row.col.f32.bf16.bf16.f32 "
        "{%0,%1,%2,%3},{%4,%5,%6,%7},{%8,%9},{%0,%1,%2,%3};"
        : "+f"(c[0]), "+f"(c[1]), "+f"(c[2]), "+f"(c[3])
        : "r"(a[0]), "r"(a[1]), "r"(a[2]), "r"(a[3]), "r"(b0), "r"(b1));
}

// ============================================================
// conversion kernels: fp32 -> bf16 hi/lo split
// ============================================================
__global__ __launch_bounds__(256) void conv_x_kernel(const float* __restrict__ x)
{
    size_t gid = (size_t)blockIdx.x * 256 + threadIdx.x;
    size_t i = gid * 4;
    float4 v = *(const float4*)(x + i);
    uint32_t bx = f2u(v.x), by = f2u(v.y), bz = f2u(v.z), bw = f2u(v.w);
    uint2 H, Lw;
    H.x = prmt_hi16(bx, by);
    H.y = prmt_hi16(bz, bw);
    Lw.x = cvt_bf16x2(v.x - __uint_as_float(bx & 0xffff0000u),
                      v.y - __uint_as_float(by & 0xffff0000u));
    Lw.y = cvt_bf16x2(v.z - __uint_as_float(bz & 0xffff0000u),
                      v.w - __uint_as_float(bw & 0xffff0000u));
    *(uint2*)(gx_hi + i) = H;
    *(uint2*)(gx_lo + i) = Lw;
}

__global__ __launch_bounds__(256) void conv_wT_kernel(const float* __restrict__ w,
                                                      int K, int N, int which)
{
    __shared__ float t[32][33];
    uint16_t* dh = which ? gwo_hi : gwi_hi;
    uint16_t* dl = which ? gwo_lo : gwi_lo;
    int n0 = blockIdx.x * 32, k0 = blockIdx.y * 32;
    int tx = threadIdx.x & 31, ty = threadIdx.x >> 5;
#pragma unroll
    for (int i = 0; i < 4; i++)
        t[ty + 8 * i][tx] = w[(size_t)(k0 + ty + 8 * i) * N + n0 + tx];
    __syncthreads();
#pragma unroll
    for (int i = 0; i < 4; i++) {
        int nn = ty + 8 * i;
        float v = t[tx][nn];
        uint32_t b = f2u(v);
        size_t idx = (size_t)(n0 + nn) * K + k0 + tx;
        dh[idx] = (uint16_t)(b >> 16);
        dl[idx] = bf16_rn(v - __uint_as_float(b & 0xffff0000u));
    }
}

// ============================================================
// GEMM bf16x3, 512 threads (16 warps, 4x4 grid, warp tile 32x32),
// cp.async 2-stage pipeline. Tile 128x128, k-chunk 64.
// ============================================================
template <int MODE>
__global__ __launch_bounds__(512, 1) void gemm_bf16_kernel(
    const float* __restrict__ bias, float* __restrict__ Cout)
{
    extern __shared__ char smp[];
    const uint32_t sbase = smem_u32(smp);
    int tid = threadIdx.x;
    int lane = tid & 31, w = tid >> 5;
    int wm = w >> 2, wn = w & 3;
    int bm = blockIdx.y, bn = blockIdx.x;

    const uint16_t* Ahi = (MODE == 0) ? gx_hi : gctx_hi;
    const uint16_t* Alo = (MODE == 0) ? gx_lo : gctx_lo;
    const uint16_t* Bhi = (MODE == 0) ? gwi_hi : gwo_hi;
    const uint16_t* Blo = (MODE == 0) ? gwi_lo : gwo_lo;

    int r = tid >> 2, g0 = (tid & 3) * 2;   // 4 threads/row, 2 16B-groups each
    size_t aoff = (size_t)(bm * 128 + r) * HIDDEN;
    size_t boff = (size_t)(bn * 128 + r) * HIDDEN;

    float acc[2][4][4];
#pragma unroll
    for (int i = 0; i < 2; i++)
#pragma unroll
        for (int j = 0; j < 4; j++)
#pragma unroll
            for (int e = 0; e < 4; e++) acc[i][j][e] = 0.f;

#define ISSUE_CHUNK(kc, buf) do {                                              \
        uint32_t dst = sbase + (uint32_t)(buf) * 65536u;                        \
        const uint16_t* ah = Ahi + aoff + (kc) * 64;                            \
        const uint16_t* al = Alo + aoff + (kc) * 64;                            \
        const uint16_t* bh = Bhi + boff + (kc) * 64;                            \
        const uint16_t* bl = Blo + boff + (kc) * 64;                            \
        _Pragma("unroll")                                                       \
        for (int i = 0; i < 2; i++) {                                           \
            uint32_t so = swz128((uint32_t)r * 128u + (uint32_t)(g0 + i) * 16u);\
            cp16(dst + so,           ah + (g0 + i) * 8);                        \
            cp16(dst + 16384u + so,  al + (g0 + i) * 8);                        \
            cp16(dst + 32768u + so,  bh + (g0 + i) * 8);                        \
            cp16(dst + 49152u + so,  bl + (g0 + i) * 8);                        \
        }                                                                       \
        cp_commit();                                                            \
    } while (0)

    ISSUE_CHUNK(0, 0);

    const int NK = HIDDEN / 64;   // 8
    for (int kc = 0; kc < NK; kc++) {
        if (kc + 1 < NK) {
            ISSUE_CHUNK(kc + 1, (kc + 1) & 1);
            cp_wait<1>();
        } else {
            cp_wait<0>();
        }
        __syncthreads();

        uint32_t abase = sbase + (uint32_t)(kc & 1) * 65536u;
        uint32_t bbase = abase + 32768u;
#pragma unroll
        for (int ks = 0; ks < 4; ks++) {
            uint32_t ah[2][4], al[2][4];
#pragma unroll
            for (int mi = 0; mi < 2; mi++) {
                uint32_t off = swz128((uint32_t)(wm * 32 + mi * 16 + (lane & 15)) * 128u
                                      + (uint32_t)(ks * 32 + ((lane & 16) ? 16 : 0)));
                ldsm4(ah[mi][0], ah[mi][1], ah[mi][2], ah[mi][3], abase + off);
                ldsm4(al[mi][0], al[mi][1], al[mi][2], al[mi][3], abase + 16384u + off);
            }
            uint32_t bh[2][4], bl[2][4];
#pragma unroll
            for (int np = 0; np < 2; np++) {
                uint32_t boffs = swz128((uint32_t)(wn * 32 + np * 16 + (lane & 7)
                                                   + ((lane & 16) ? 8 : 0)) * 128u
                                        + (uint32_t)(ks * 32 + ((lane & 8) ? 16 : 0)));
                ldsm4(bh[np][0], bh[np][1], bh[np][2], bh[np][3], bbase + boffs);
                ldsm4(bl[np][0], bl[np][1], bl[np][2], bl[np][3], bbase + 16384u + boffs);
            }
#pragma unroll
            for (int np = 0; np < 2; np++) {
#pragma unroll
                for (int mi = 0; mi < 2; mi++) {
                    mma_bf16(acc[mi][2 * np],     ah[mi], bh[np][0], bh[np][1]);
                    mma_bf16(acc[mi][2 * np + 1], ah[mi], bh[np][2], bh[np][3]);
                }
#pragma unroll
                for (int mi = 0; mi < 2; mi++) {
                    mma_bf16(acc[mi][2 * np],     ah[mi], bl[np][0], bl[np][1]);
                    mma_bf16(acc[mi][2 * np + 1], ah[mi], bl[np][2], bl[np][3]);
                }
#pragma unroll
                for (int mi = 0; mi < 2; mi++) {
                    mma_bf16(acc[mi][2 * np],     al[mi], bh[np][0], bh[np][1]);
                    mma_bf16(acc[mi][2 * np + 1], al[mi], bh[np][2], bh[np][3]);
                }
            }
        }
        __syncthreads();
    }
#undef ISSUE_CHUNK

    // ---- epilogue ----
#pragma unroll
    for (int mi = 0; mi < 2; mi++) {
        int r0 = bm * 128 + wm * 32 + mi * 16 + (lane >> 2);
#pragma unroll
        for (int nj = 0; nj < 4; nj++) {
            int c0 = bn * 128 + wn * 32 + nj * 8 + 2 * (lane & 3);
            float bb0 = __ldg(bias + c0), bb1 = __ldg(bias + c0 + 1);
            float v0 = acc[mi][nj][0] + bb0, v1 = acc[mi][nj][1] + bb1;
            float v2 = acc[mi][nj][2] + bb0, v3 = acc[mi][nj][3] + bb1;
            if (MODE == 0) {
                int which = c0 >> 9, h = (c0 >> 6) & 7, d = c0 & 63;
                uint16_t* dh = (which == 0) ? gq_hi : (which == 1) ? gk_hi : gv_hi;
                uint16_t* dl = (which == 0) ? gq_lo : (which == 1) ? gk_lo : gv_lo;
                int b = r0 >> 12;
                size_t base0 = ((size_t)((b * 8 + h) * L_ + (r0 & 4095))) * 64 + d;
                size_t base1 = base0 + 8 * 64;
                uint32_t u0 = f2u(v0), u1 = f2u(v1), u2 = f2u(v2), u3 = f2u(v3);
                *(uint32_t*)(dh + base0) = prmt_hi16(u0, u1);
                *(uint32_t*)(dl + base0) =
                    cvt_bf16x2(v0 - __uint_as_float(u0 & 0xffff0000u),
                               v1 - __uint_as_float(u1 & 0xffff0000u));
                *(uint32_t*)(dh + base1) = prmt_hi16(u2, u3);
                *(uint32_t*)(dl + base1) =
                    cvt_bf16x2(v2 - __uint_as_float(u2 & 0xffff0000u),
                               v3 - __uint_as_float(u3 & 0xffff0000u));
            } else {
                *(float2*)(Cout + (size_t)r0 * HIDDEN + c0) = make_float2(v0, v1);
                *(float2*)(Cout + (size_t)(r0 + 8) * HIDDEN + c0) = make_float2(v2, v3);
            }
        }
    }
}

// ============================================================
// Attention SMEM: Q 32KB; K/V double buffer (2 x 32KB). 96KB.
// ============================================================
#define SQHI 0u
#define SQLO 16384u
#define SKV0 32768u
#define ATTN_SMEM 98304

// 2 CTAs/SM target: <=128 regs. Q-lo fragments loaded on demand.
__global__ __launch_bounds__(256, 2) void attn_mma_kernel()
{
    extern __shared__ char smp[];
    const uint32_t sbase = smem_u32(smp);
    int tid = threadIdx.x;
    int w = tid >> 5, lane = tid & 31;

    int bh = blockIdx.x;                            // b*8 + h
    int qt = (int)gridDim.y - 1 - (int)blockIdx.y;  // heavy tiles first
    int nkt = 2 * qt + 2;                           // 64-key tiles

    int ct = tid & 127;
    int rr = ct >> 1, g0 = (ct & 1) * 4;
    const uint16_t* srch = (tid < 128) ? gk_hi : gv_hi;
    const uint16_t* srcl = (tid < 128) ? gk_lo : gv_lo;
    uint32_t dsel = (tid < 128) ? 0u : 16384u;

#define ISSUE_KV(kt, buf) do {                                                   \
        uint32_t dst = sbase + SKV0 + (uint32_t)(buf) * 32768u + dsel;           \
        const uint16_t* sh = srch + ((size_t)bh * L_ + (size_t)(kt) * 64 + rr) * 64; \
        const uint16_t* sl = srcl + ((size_t)bh * L_ + (size_t)(kt) * 64 + rr) * 64; \
        _Pragma("unroll")                                                        \
        for (int i = 0; i < 4; i++) {                                            \
            uint32_t so = swz128((uint32_t)rr * 128u + (uint32_t)(g0 + i) * 16u);\
            cp16(dst + so,          sh + (g0 + i) * 8);                          \
            cp16(dst + 8192u + so,  sl + (g0 + i) * 8);                          \
        }                                                                        \
        cp_commit();                                                             \
    } while (0)

    // Prologue: Q tile copy + first K/V issue
    {
        const uint4* qh4 = (const uint4*)(gq_hi + ((size_t)bh * L_ + (size_t)qt * 128 + (tid >> 1)) * 64);
        const uint4* ql4 = (const uint4*)(gq_lo + ((size_t)bh * L_ + (size_t)qt * 128 + (tid >> 1)) * 64);
        int qg0 = (tid & 1) * 4;
#pragma unroll
        for (int i = 0; i < 4; i++) {
            uint32_t so = swz128((uint32_t)(tid >> 1) * 128u + (uint32_t)(qg0 + i) * 16u);
            *(uint4*)(smp + SQHI + so) = qh4[qg0 + i];
            *(uint4*)(smp + SQLO + so) = ql4[qg0 + i];
        }
    }
    ISSUE_KV(0, 0);
    __syncthreads();

    int arow = 16 * w + (lane & 15);
    // Q-hi fragments resident; Q-lo loaded per ks on demand
    uint32_t qh[4][4];
    uint32_t qloff[4];
    {
#pragma unroll
        for (int ks = 0; ks < 4; ks++) {
            uint32_t off = swz128((uint32_t)arow * 128u
                                  + (uint32_t)(ks * 32 + ((lane & 16) ? 16 : 0)));
            ldsm4(qh[ks][0], qh[ks][1], qh[ks][2], qh[ks][3], sbase + SQHI + off);
            qloff[ks] = sbase + SQLO + off;
        }
    }

    float oc[8][4];
#pragma unroll
    for (int n = 0; n < 8; n++)
#pragma unroll
        for (int j = 0; j < 4; j++) oc[n][j] = 0.f;
    float lsum0 = 0.f, lsum1 = 0.f;

    const float Cc = 0.18033688011112042f;  // (1/8) * log2(e)
    int row0 = qt * 128 + 16 * w + (lane >> 2);
    int row1 = row0 + 8;

    for (int kt = 0; kt < nkt; ++kt) {
        if (kt + 1 < nkt) {
            ISSUE_KV(kt + 1, (kt + 1) & 1);
            cp_wait<1>();
        } else {
            cp_wait<0>();
        }
        __syncthreads();

        uint32_t kvb = sbase + SKV0 + (uint32_t)(kt & 1) * 32768u;

        // ---- S = Q K^T ----
        float sc[8][4];
#pragma unroll
        for (int n = 0; n < 8; n++)
#pragma unroll
            for (int j = 0; j < 4; j++) sc[n][j] = 0.f;

#pragma unroll
        for (int ks = 0; ks < 4; ks++) {
            uint32_t ql[4];
            ldsm4(ql[0], ql[1], ql[2], ql[3], qloff[ks]);
#pragma unroll
            for (int npp = 0; npp < 2; npp++) {
                int key0 = (2 * npp) * 16 + (lane & 7) + ((lane & 16) ? 8 : 0);
                uint32_t col = (uint32_t)(ks * 32 + ((lane & 8) ? 16 : 0));
                uint32_t off0 = swz128((uint32_t)key0 * 128u + col);
                uint32_t off1 = swz128((uint32_t)(key0 + 16) * 128u + col);
                uint32_t h00, h01, h02, h03, l00, l01, l02, l03;
                uint32_t h10, h11, h12, h13, l10, l11, l12, l13;
                ldsm4(h00, h01, h02, h03, kvb + off0);
                ldsm4(l00, l01, l02, l03, kvb + 8192u + off0);
                ldsm4(h10, h11, h12, h13, kvb + off1);
                ldsm4(l10, l11, l12, l13, kvb + 8192u + off1);
                float* s0 = sc[4 * npp + 0];
                float* s1 = sc[4 * npp + 1];
                float* s2 = sc[4 * npp + 2];
                float* s3 = sc[4 * npp + 3];
                mma_bf16(s0, qh[ks], h00, h01);
                mma_bf16(s1, qh[ks], h02, h03);
                mma_bf16(s2, qh[ks], h10, h11);
                mma_bf16(s3, qh[ks], h12, h13);
                mma_bf16(s0, qh[ks], l00, l01);
                mma_bf16(s1, qh[ks], l02, l03);
                mma_bf16(s2, qh[ks], l10, l11);
                mma_bf16(s3, qh[ks], l12, l13);
                mma_bf16(s0, ql, h00, h01);
                mma_bf16(s1, ql, h02, h03);
                mma_bf16(s2, ql, h10, h11);
                mma_bf16(s3, ql, h12, h13);
            }
        }

        // ---- softmax (unnormalized) ----
        bool edge = (kt == 0) || (kt >= 2 * qt);
        int colb = kt * 64 + 2 * (lane & 3);
#pragma unroll
        for (int n = 0; n < 8; n++) {
            float e0 = ex2f(sc[n][0] * Cc);
            float e1 = ex2f(sc[n][1] * Cc);
            float e2 = ex2f(sc[n][2] * Cc);
            float e3 = ex2f(sc[n][3] * Cc);
            if (edge) {
                int c0 = colb + 8 * n, c1 = c0 + 1;
                bool k00 = (c0 <= row0) && (c0 >= PREFIX || row0 < PREFIX);
                bool k01 = (c1 <= row0) && (c1 >= PREFIX || row0 < PREFIX);
                bool k10 = (c0 <= row1) && (c0 >= PREFIX || row1 < PREFIX);
                bool k11 = (c1 <= row1) && (c1 >= PREFIX || row1 < PREFIX);
                e0 = k00 ? e0 : 0.f;
                e1 = k01 ? e1 : 0.f;
                e2 = k10 ? e2 : 0.f;
                e3 = k11 ? e3 : 0.f;
            }
            sc[n][0] = e0; sc[n][1] = e1; sc[n][2] = e2; sc[n][3] = e3;
            lsum0 += e0 + e1;
            lsum1 += e2 + e3;
        }

        // ---- O += P V ----
#pragma unroll
        for (int t = 0; t < 4; t++) {
            uint32_t ph[4], pl[4];
            {
                float* cA = sc[2 * t];
                float* cB = sc[2 * t + 1];
                uint32_t a0 = f2u(cA[0]), a1 = f2u(cA[1]);
                uint32_t a2 = f2u(cA[2]), a3 = f2u(cA[3]);
                uint32_t b0 = f2u(cB[0]), b1 = f2u(cB[1]);
                uint32_t b2 = f2u(cB[2]), b3 = f2u(cB[3]);
                ph[0] = prmt_hi16(a0, a1);
                ph[1] = prmt_hi16(a2, a3);
                ph[2] = prmt_hi16(b0, b1);
                ph[3] = prmt_hi16(b2, b3);
                pl[0] = cvt_bf16x2(cA[0] - __uint_as_float(a0 & 0xffff0000u),
                                   cA[1] - __uint_as_float(a1 & 0xffff0000u));
                pl[1] = cvt_bf16x2(cA[2] - __uint_as_float(a2 & 0xffff0000u),
                                   cA[3] - __uint_as_float(a3 & 0xffff0000u));
                pl[2] = cvt_bf16x2(cB[0] - __uint_as_float(b0 & 0xffff0000u),
                                   cB[1] - __uint_as_float(b1 & 0xffff0000u));
                pl[3] = cvt_bf16x2(cB[2] - __uint_as_float(b2 & 0xffff0000u),
                                   cB[3] - __uint_as_float(b3 & 0xffff0000u));
            }
            int key = t * 16 + (lane & 7) + ((lane & 8) ? 8 : 0);
#pragma unroll
            for (int dpp = 0; dpp < 2; dpp++) {
                uint32_t col0 = (uint32_t)((2 * dpp) * 32 + ((lane & 16) ? 16 : 0));
                uint32_t off0 = swz128((uint32_t)key * 128u + col0);
                uint32_t off1 = swz128((uint32_t)key * 128u + col0 + 32u);
                uint32_t h00, h01, h02, h03, l00, l01, l02, l03;
                uint32_t h10, h11, h12, h13, l10, l11, l12, l13;
                ldsm4t(h00, h01, h02, h03, kvb + 16384u + off0);
                ldsm4t(l00, l01, l02, l03, kvb + 24576u + off0);
                ldsm4t(h10, h11, h12, h13, kvb + 16384u + off1);
                ldsm4t(l10, l11, l12, l13, kvb + 24576u + off1);
                float* o0 = oc[4 * dpp + 0];
                float* o1 = oc[4 * dpp + 1];
                float* o2 = oc[4 * dpp + 2];
                float* o3 = oc[4 * dpp + 3];
                mma_bf16(o0, ph, h00, h01);
                mma_bf16(o1, ph, h02, h03);
                mma_bf16(o2, ph, h10, h11);
                mma_bf16(o3, ph, h12, h13);
                mma_bf16(o0, ph, l00, l01);
                mma_bf16(o1, ph, l02, l03);
                mma_bf16(o2, ph, l10, l11);
                mma_bf16(o3, ph, l12, l13);
                mma_bf16(o0, pl, h00, h01);
                mma_bf16(o1, pl, h02, h03);
                mma_bf16(o2, pl, h10, h11);
                mma_bf16(o3, pl, h12, h13);
            }
        }
        __syncthreads();
    }
#undef ISSUE_KV

    // lane reduction of lsum
    lsum0 += __shfl_xor_sync(0xffffffffu, lsum0, 1);
    lsum0 += __shfl_xor_sync(0xffffffffu, lsum0, 2);
    lsum1 += __shfl_xor_sync(0xffffffffu, lsum1, 1);
    lsum1 += __shfl_xor_sync(0xffffffffu, lsum1, 2);
    float inv0 = 1.f / lsum0, inv1 = 1.f / lsum1;

    // store ctx as bf16 hi/lo
    int b = bh >> 3, h = bh & 7;
    size_t r0base = (size_t)(b * L_ + row0) * HIDDEN + h * 64;
    size_t r1base = (size_t)(b * L_ + row1) * HIDDEN + h * 64;
#pragma unroll
    for (int n = 0; n < 8; n++) {
        int d = 8 * n + 2 * (lane & 3);
        float v0 = oc[n][0] * inv0, v1 = oc[n][1] * inv0;
        float v2 = oc[n][2] * inv1, v3 = oc[n][3] * inv1;
        uint32_t u0 = f2u(v0), u1 = f2u(v1), u2 = f2u(v2), u3 = f2u(v3);
        *(uint32_t*)(gctx_hi + r0base + d) = prmt_hi16(u0, u1);
        *(uint32_t*)(gctx_lo + r0base + d) =
            cvt_bf16x2(v0 - __uint_as_float(u0 & 0xffff0000u),
                       v1 - __uint_as_float(u1 & 0xffff0000u));
        *(uint32_t*)(gctx_hi + r1base + d) = prmt_hi16(u2, u3);
        *(uint32_t*)(gctx_lo + r1base + d) =
            cvt_bf16x2(v2 - __uint_as_float(u2 & 0xffff0000u),
                       v3 - __uint_as_float(u3 & 0xffff0000u));
    }
}

// ============================================================
extern "C" void kernel_launch(void* const* d_in, const int* in_sizes, int n_in,
                              void* d_out, int out_size)
{
    const float* x     = (const float*)d_in[0];
    const float* w_in  = (const float*)d_in[1];
    const float* b_in  = (const float*)d_in[2];
    const float* w_out = (const float*)d_in[3];
    const float* b_out = (const float*)d_in[4];
    float* out = (float*)d_out;

    conv_x_kernel<<<(M_ROWS * HIDDEN / 4) / 256, 256>>>(x);
    conv_wT_kernel<<<dim3(3 * HIDDEN / 32, HIDDEN / 32), 256>>>(w_in, HIDDEN, 3 * HIDDEN, 0);
    conv_wT_kernel<<<dim3(HIDDEN / 32, HIDDEN / 32), 256>>>(w_out, HIDDEN, HIDDEN, 1);

    cudaFuncSetAttribute(gemm_bf16_kernel<0>,
                         cudaFuncAttributeMaxDynamicSharedMemorySize, 131072);
    gemm_bf16_kernel<0><<<dim3(12, 64), 512, 131072>>>(b_in, nullptr);

    cudaFuncSetAttribute(attn_mma_kernel,
                         cudaFuncAttributeMaxDynamicSharedMemorySize, ATTN_SMEM);
    attn_mma_kernel<<<dim3(16, 32), 256, ATTN_SMEM>>>();

    cudaFuncSetAttribute(gemm_bf16_kernel<1>,
                         cudaFuncAttributeMaxDynamicSharedMemorySize, 131072);
    gemm_bf16_kernel<1><<<dim3(4, 64), 512, 131072>>>(b_out, out);
}

// round 9
// speedup vs baseline: 1.0849x; 1.0001x over previous
#include <cuda_runtime.h>
#include <cstdint>

typedef unsigned long long ull;

#define B_      2
#define L_      4096
#define HIDDEN  512
#define HEADS   8
#define HD      64
#define PREFIX  1
#define M_ROWS  (B_ * L_)        // 8192

// ---- bf16 hi/lo split storage (allocation-free: __device__ globals) ----
__device__ __align__(16) uint16_t gx_hi[M_ROWS * HIDDEN],  gx_lo[M_ROWS * HIDDEN];
__device__ __align__(16) uint16_t gwi_hi[3 * HIDDEN * HIDDEN], gwi_lo[3 * HIDDEN * HIDDEN];
__device__ __align__(16) uint16_t gwo_hi[HIDDEN * HIDDEN], gwo_lo[HIDDEN * HIDDEN];
__device__ __align__(16) uint16_t gq_hi[M_ROWS * HIDDEN],  gq_lo[M_ROWS * HIDDEN];
__device__ __align__(16) uint16_t gk_hi[M_ROWS * HIDDEN],  gk_lo[M_ROWS * HIDDEN];
__device__ __align__(16) uint16_t gv_hi[M_ROWS * HIDDEN],  gv_lo[M_ROWS * HIDDEN];
__device__ __align__(16) uint16_t gctx_hi[M_ROWS * HIDDEN], gctx_lo[M_ROWS * HIDDEN];

// ============================================================
// helpers
// ============================================================
__device__ __forceinline__ uint32_t smem_u32(const void* p) {
    uint32_t a;
    asm("{ .reg .u64 t; cvta.to.shared.u64 t, %1; cvt.u32.u64 %0, t; }" : "=r"(a) : "l"(p));
    return a;
}
__device__ __forceinline__ uint32_t f2u(float x) { return __float_as_uint(x); }
__device__ __forceinline__ uint32_t prmt_hi16(uint32_t a, uint32_t b) {
    uint32_t r; asm("prmt.b32 %0,%1,%2,0x7632;" : "=r"(r) : "r"(a), "r"(b)); return r;
}
__device__ __forceinline__ uint32_t cvt_bf16x2(float lo, float hi) {
    uint32_t r; asm("cvt.rn.bf16x2.f32 %0,%1,%2;" : "=r"(r) : "f"(hi), "f"(lo)); return r;
}
__device__ __forceinline__ uint16_t bf16_rn(float x) {
    uint16_t u; asm("cvt.rn.bf16.f32 %0,%1;" : "=h"(u) : "f"(x)); return u;
}
__device__ __forceinline__ float ex2f(float x) {
    float r; asm("ex2.approx.f32 %0,%1;" : "=f"(r) : "f"(x)); return r;
}
__device__ __forceinline__ uint32_t swz128(uint32_t o) { return o ^ ((o >> 3) & 0x70u); }

__device__ __forceinline__ void cp16(uint32_t dst, const void* src) {
    asm volatile("cp.async.cg.shared.global [%0], [%1], 16;" :: "r"(dst), "l"(src) : "memory");
}
__device__ __forceinline__ void cp_commit() {
    asm volatile("cp.async.commit_group;" ::: "memory");
}
template <int N> __device__ __forceinline__ void cp_wait() {
    asm volatile("cp.async.wait_group %0;" :: "n"(N) : "memory");
}

__device__ __forceinline__ void ldsm4(uint32_t& r0, uint32_t& r1, uint32_t& r2, uint32_t& r3,
                                      uint32_t addr) {
    asm volatile("ldmatrix.sync.aligned.m8n8.x4.shared.b16 {%0,%1,%2,%3}, [%4];"
                 : "=r"(r0), "=r"(r1), "=r"(r2), "=r"(r3) : "r"(addr));
}
__device__ __forceinline__ void ldsm4t(uint32_t& r0, uint32_t& r1, uint32_t& r2, uint32_t& r3,
                                       uint32_t addr) {
    asm volatile("ldmatrix.sync.aligned.m8n8.x4.trans.shared.b16 {%0,%1,%2,%3}, [%4];"
                 : "=r"(r0), "=r"(r1), "=r"(r2), "=r"(r3) : "r"(addr));
}
__device__ __forceinline__ void mma_bf16(float* c, const uint32_t* a, uint32_t b0, uint32_t b1) {
    asm volatile(
        "mma.sync.aligned.m16n8k16.row.col.f32.bf16.bf16.f32 "
        "{%0,%1,%2,%3},{%4,%5,%6,%7},{%8,%9},{%0,%1,%2,%3};"
        : "+f"(c[0]), "+f"(c[1]), "+f"(c[2]), "+f"(c[3])
        : "r"(a[0]), "r"(a[1]), "r"(a[2]), "r"(a[3]), "r"(b0), "r"(b1));
}

// ============================================================
// conversion kernels: fp32 -> bf16 hi/lo split
// ============================================================
__global__ __launch_bounds__(256) void conv_x_kernel(const float* __restrict__ x)
{
    size_t gid = (size_t)blockIdx.x * 256 + threadIdx.x;
    size_t i = gid * 4;
    float4 v = *(const float4*)(x + i);
    uint32_t bx = f2u(v.x), by = f2u(v.y), bz = f2u(v.z), bw = f2u(v.w);
    uint2 H, Lw;
    H.x = prmt_hi16(bx, by);
    H.y = prmt_hi16(bz, bw);
    Lw.x = cvt_bf16x2(v.x - __uint_as_float(bx & 0xffff0000u),
                      v.y - __uint_as_float(by & 0xffff0000u));
    Lw.y = cvt_bf16x2(v.z - __uint_as_float(bz & 0xffff0000u),
                      v.w - __uint_as_float(bw & 0xffff0000u));
    *(uint2*)(gx_hi + i) = H;
    *(uint2*)(gx_lo + i) = Lw;
}

__global__ __launch_bounds__(256) void conv_wT_kernel(const float* __restrict__ w,
                                                      int K, int N, int which)
{
    __shared__ float t[32][33];
    uint16_t* dh = which ? gwo_hi : gwi_hi;
    uint16_t* dl = which ? gwo_lo : gwi_lo;
    int n0 = blockIdx.x * 32, k0 = blockIdx.y * 32;
    int tx = threadIdx.x & 31, ty = threadIdx.x >> 5;
#pragma unroll
    for (int i = 0; i < 4; i++)
        t[ty + 8 * i][tx] = w[(size_t)(k0 + ty + 8 * i) * N + n0 + tx];
    __syncthreads();
#pragma unroll
    for (int i = 0; i < 4; i++) {
        int nn = ty + 8 * i;
        float v = t[tx][nn];
        uint32_t b = f2u(v);
        size_t idx = (size_t)(n0 + nn) * K + k0 + tx;
        dh[idx] = (uint16_t)(b >> 16);
        dl[idx] = bf16_rn(v - __uint_as_float(b & 0xffff0000u));
    }
}

// ============================================================
// GEMM bf16x3, 256 threads, tile 128x64, 2 CTAs/SM.
// Warp grid 4x2, warp tile 32x32. cp.async 2-stage pipeline.
// Stage (48KB): {AHI 0, ALO 16K, BHI 32K, BLO 40K}; stride 49152.
// ============================================================
#define GSTAGE 49152u

template <int MODE>
__global__ __launch_bounds__(256, 2) void gemm_bf16_kernel(
    const float* __restrict__ bias, float* __restrict__ Cout)
{
    extern __shared__ char smp[];
    const uint32_t sbase = smem_u32(smp);
    int tid = threadIdx.x;
    int lane = tid & 31, w = tid >> 5;
    int wm = w >> 1, wn = w & 1;
    int bm = blockIdx.y, bn = blockIdx.x;

    const uint16_t* Ahi = (MODE == 0) ? gx_hi : gctx_hi;
    const uint16_t* Alo = (MODE == 0) ? gx_lo : gctx_lo;
    const uint16_t* Bhi = (MODE == 0) ? gwi_hi : gwo_hi;
    const uint16_t* Blo = (MODE == 0) ? gwi_lo : gwo_lo;

    // A loader: 2 thr/row, 4 groups each; B loader: 4 thr/row, 2 groups each
    int ra = tid >> 1, ga = (tid & 1) * 4;
    int rb = tid >> 2, gb = (tid & 3) * 2;
    size_t aoff = (size_t)(bm * 128 + ra) * HIDDEN;
    size_t boff = (size_t)(bn * 64 + rb) * HIDDEN;

    float acc[2][4][4];
#pragma unroll
    for (int i = 0; i < 2; i++)
#pragma unroll
        for (int j = 0; j < 4; j++)
#pragma unroll
            for (int e = 0; e < 4; e++) acc[i][j][e] = 0.f;

#define ISSUE_CHUNK(kc, buf) do {                                               \
        uint32_t dst = sbase + (uint32_t)(buf) * GSTAGE;                         \
        const uint16_t* ah = Ahi + aoff + (kc) * 64;                             \
        const uint16_t* al = Alo + aoff + (kc) * 64;                             \
        _Pragma("unroll")                                                        \
        for (int i = 0; i < 4; i++) {                                            \
            uint32_t so = swz128((uint32_t)ra * 128u + (uint32_t)(ga + i) * 16u);\
            cp16(dst + so,          ah + (ga + i) * 8);                          \
            cp16(dst + 16384u + so, al + (ga + i) * 8);                          \
        }                                                                        \
        const uint16_t* bh = Bhi + boff + (kc) * 64;                             \
        const uint16_t* bl = Blo + boff + (kc) * 64;                             \
        _Pragma("unroll")                                                        \
        for (int i = 0; i < 2; i++) {                                            \
            uint32_t so = swz128((uint32_t)rb * 128u + (uint32_t)(gb + i) * 16u);\
            cp16(dst + 32768u + so, bh + (gb + i) * 8);                          \
            cp16(dst + 40960u + so, bl + (gb + i) * 8);                          \
        }                                                                        \
        cp_commit();                                                             \
    } while (0)

    ISSUE_CHUNK(0, 0);

    const int NK = HIDDEN / 64;   // 8
    for (int kc = 0; kc < NK; kc++) {
        if (kc + 1 < NK) {
            ISSUE_CHUNK(kc + 1, (kc + 1) & 1);
            cp_wait<1>();
        } else {
            cp_wait<0>();
        }
        __syncthreads();

        uint32_t abase = sbase + (uint32_t)(kc & 1) * GSTAGE;
        uint32_t bbase = abase + 32768u;
#pragma unroll
        for (int ks = 0; ks < 4; ks++) {
            uint32_t ah[2][4], al[2][4];
#pragma unroll
            for (int mi = 0; mi < 2; mi++) {
                uint32_t off = swz128((uint32_t)(wm * 32 + mi * 16 + (lane & 15)) * 128u
                                      + (uint32_t)(ks * 32 + ((lane & 16) ? 16 : 0)));
                ldsm4(ah[mi][0], ah[mi][1], ah[mi][2], ah[mi][3], abase + off);
                ldsm4(al[mi][0], al[mi][1], al[mi][2], al[mi][3], abase + 16384u + off);
            }
            uint32_t bh[2][4], bl[2][4];
#pragma unroll
            for (int np = 0; np < 2; np++) {
                uint32_t boffs = swz128((uint32_t)(wn * 32 + np * 16 + (lane & 7)
                                                   + ((lane & 16) ? 8 : 0)) * 128u
                                        + (uint32_t)(ks * 32 + ((lane & 8) ? 16 : 0)));
                ldsm4(bh[np][0], bh[np][1], bh[np][2], bh[np][3], bbase + boffs);
                ldsm4(bl[np][0], bl[np][1], bl[np][2], bl[np][3], bbase + 8192u + boffs);
            }
#pragma unroll
            for (int np = 0; np < 2; np++) {
#pragma unroll
                for (int mi = 0; mi < 2; mi++) {
                    mma_bf16(acc[mi][2 * np],     ah[mi], bh[np][0], bh[np][1]);
                    mma_bf16(acc[mi][2 * np + 1], ah[mi], bh[np][2], bh[np][3]);
                }
#pragma unroll
                for (int mi = 0; mi < 2; mi++) {
                    mma_bf16(acc[mi][2 * np],     ah[mi], bl[np][0], bl[np][1]);
                    mma_bf16(acc[mi][2 * np + 1], ah[mi], bl[np][2], bl[np][3]);
                }
#pragma unroll
                for (int mi = 0; mi < 2; mi++) {
                    mma_bf16(acc[mi][2 * np],     al[mi], bh[np][0], bh[np][1]);
                    mma_bf16(acc[mi][2 * np + 1], al[mi], bh[np][2], bh[np][3]);
                }
            }
        }
        __syncthreads();
    }
#undef ISSUE_CHUNK

    // ---- epilogue ----
#pragma unroll
    for (int mi = 0; mi < 2; mi++) {
        int r0 = bm * 128 + wm * 32 + mi * 16 + (lane >> 2);
#pragma unroll
        for (int nj = 0; nj < 4; nj++) {
            int c0 = bn * 64 + wn * 32 + nj * 8 + 2 * (lane & 3);
            float bb0 = __ldg(bias + c0), bb1 = __ldg(bias + c0 + 1);
            float v0 = acc[mi][nj][0] + bb0, v1 = acc[mi][nj][1] + bb1;
            float v2 = acc[mi][nj][2] + bb0, v3 = acc[mi][nj][3] + bb1;
            if (MODE == 0) {
                int which = c0 >> 9, h = (c0 >> 6) & 7, d = c0 & 63;
                uint16_t* dh = (which == 0) ? gq_hi : (which == 1) ? gk_hi : gv_hi;
                uint16_t* dl = (which == 0) ? gq_lo : (which == 1) ? gk_lo : gv_lo;
                int b = r0 >> 12;
                size_t base0 = ((size_t)((b * 8 + h) * L_ + (r0 & 4095))) * 64 + d;
                size_t base1 = base0 + 8 * 64;
                uint32_t u0 = f2u(v0), u1 = f2u(v1), u2 = f2u(v2), u3 = f2u(v3);
                *(uint32_t*)(dh + base0) = prmt_hi16(u0, u1);
                *(uint32_t*)(dl + base0) =
                    cvt_bf16x2(v0 - __uint_as_float(u0 & 0xffff0000u),
                               v1 - __uint_as_float(u1 & 0xffff0000u));
                *(uint32_t*)(dh + base1) = prmt_hi16(u2, u3);
                *(uint32_t*)(dl + base1) =
                    cvt_bf16x2(v2 - __uint_as_float(u2 & 0xffff0000u),
                               v3 - __uint_as_float(u3 & 0xffff0000u));
            } else {
                *(float2*)(Cout + (size_t)r0 * HIDDEN + c0) = make_float2(v0, v1);
                *(float2*)(Cout + (size_t)(r0 + 8) * HIDDEN + c0) = make_float2(v2, v3);
            }
        }
    }
}

// ============================================================
// Attention SMEM: Q 32KB; K/V double buffer (2 x 32KB). 96KB.
// ============================================================
#define SQHI 0u
#define SQLO 16384u
#define SKV0 32768u
#define ATTN_SMEM 98304

// 2 CTAs/SM: <=128 regs. Q-lo fragments loaded on demand.
__global__ __launch_bounds__(256, 2) void attn_mma_kernel()
{
    extern __shared__ char smp[];
    const uint32_t sbase = smem_u32(smp);
    int tid = threadIdx.x;
    int w = tid >> 5, lane = tid & 31;

    int bh = blockIdx.x;                            // b*8 + h
    int qt = (int)gridDim.y - 1 - (int)blockIdx.y;  // heavy tiles first
    int nkt = 2 * qt + 2;                           // 64-key tiles

    int ct = tid & 127;
    int rr = ct >> 1, g0 = (ct & 1) * 4;
    const uint16_t* srch = (tid < 128) ? gk_hi : gv_hi;
    const uint16_t* srcl = (tid < 128) ? gk_lo : gv_lo;
    uint32_t dsel = (tid < 128) ? 0u : 16384u;

#define ISSUE_KV(kt, buf) do {                                                   \
        uint32_t dst = sbase + SKV0 + (uint32_t)(buf) * 32768u + dsel;           \
        const uint16_t* sh = srch + ((size_t)bh * L_ + (size_t)(kt) * 64 + rr) * 64; \
        const uint16_t* sl = srcl + ((size_t)bh * L_ + (size_t)(kt) * 64 + rr) * 64; \
        _Pragma("unroll")                                                        \
        for (int i = 0; i < 4; i++) {                                            \
            uint32_t so = swz128((uint32_t)rr * 128u + (uint32_t)(g0 + i) * 16u);\
            cp16(dst + so,          sh + (g0 + i) * 8);                          \
            cp16(dst + 8192u + so,  sl + (g0 + i) * 8);                          \
        }                                                                        \
        cp_commit();                                                             \
    } while (0)

    // Prologue: Q tile copy + first K/V issue
    {
        const uint4* qh4 = (const uint4*)(gq_hi + ((size_t)bh * L_ + (size_t)qt * 128 + (tid >> 1)) * 64);
        const uint4* ql4 = (const uint4*)(gq_lo + ((size_t)bh * L_ + (size_t)qt * 128 + (tid >> 1)) * 64);
        int qg0 = (tid & 1) * 4;
#pragma unroll
        for (int i = 0; i < 4; i++) {
            uint32_t so = swz128((uint32_t)(tid >> 1) * 128u + (uint32_t)(qg0 + i) * 16u);
            *(uint4*)(smp + SQHI + so) = qh4[qg0 + i];
            *(uint4*)(smp + SQLO + so) = ql4[qg0 + i];
        }
    }
    ISSUE_KV(0, 0);
    __syncthreads();

    int arow = 16 * w + (lane & 15);
    uint32_t qh[4][4];
    uint32_t qloff[4];
    {
#pragma unroll
        for (int ks = 0; ks < 4; ks++) {
            uint32_t off = swz128((uint32_t)arow * 128u
                                  + (uint32_t)(ks * 32 + ((lane & 16) ? 16 : 0)));
            ldsm4(qh[ks][0], qh[ks][1], qh[ks][2], qh[ks][3], sbase + SQHI + off);
            qloff[ks] = sbase + SQLO + off;
        }
    }

    float oc[8][4];
#pragma unroll
    for (int n = 0; n < 8; n++)
#pragma unroll
        for (int j = 0; j < 4; j++) oc[n][j] = 0.f;
    float lsum0 = 0.f, lsum1 = 0.f;

    const float Cc = 0.18033688011112042f;  // (1/8) * log2(e)
    int row0 = qt * 128 + 16 * w + (lane >> 2);
    int row1 = row0 + 8;

    for (int kt = 0; kt < nkt; ++kt) {
        if (kt + 1 < nkt) {
            ISSUE_KV(kt + 1, (kt + 1) & 1);
            cp_wait<1>();
        } else {
            cp_wait<0>();
        }
        __syncthreads();

        uint32_t kvb = sbase + SKV0 + (uint32_t)(kt & 1) * 32768u;

        // ---- S = Q K^T ----
        float sc[8][4];
#pragma unroll
        for (int n = 0; n < 8; n++)
#pragma unroll
            for (int j = 0; j < 4; j++) sc[n][j] = 0.f;

#pragma unroll
        for (int ks = 0; ks < 4; ks++) {
            uint32_t ql[4];
            ldsm4(ql[0], ql[1], ql[2], ql[3], qloff[ks]);
#pragma unroll
            for (int npp = 0; npp < 2; npp++) {
                int key0 = (2 * npp) * 16 + (lane & 7) + ((lane & 16) ? 8 : 0);
                uint32_t col = (uint32_t)(ks * 32 + ((lane & 8) ? 16 : 0));
                uint32_t off0 = swz128((uint32_t)key0 * 128u + col);
                uint32_t off1 = swz128((uint32_t)(key0 + 16) * 128u + col);
                uint32_t h00, h01, h02, h03, l00, l01, l02, l03;
                uint32_t h10, h11, h12, h13, l10, l11, l12, l13;
                ldsm4(h00, h01, h02, h03, kvb + off0);
                ldsm4(l00, l01, l02, l03, kvb + 8192u + off0);
                ldsm4(h10, h11, h12, h13, kvb + off1);
                ldsm4(l10, l11, l12, l13, kvb + 8192u + off1);
                float* s0 = sc[4 * npp + 0];
                float* s1 = sc[4 * npp + 1];
                float* s2 = sc[4 * npp + 2];
                float* s3 = sc[4 * npp + 3];
                mma_bf16(s0, qh[ks], h00, h01);
                mma_bf16(s1, qh[ks], h02, h03);
                mma_bf16(s2, qh[ks], h10, h11);
                mma_bf16(s3, qh[ks], h12, h13);
                mma_bf16(s0, qh[ks], l00, l01);
                mma_bf16(s1, qh[ks], l02, l03);
                mma_bf16(s2, qh[ks], l10, l11);
                mma_bf16(s3, qh[ks], l12, l13);
                mma_bf16(s0, ql, h00, h01);
                mma_bf16(s1, ql, h02, h03);
                mma_bf16(s2, ql, h10, h11);
                mma_bf16(s3, ql, h12, h13);
            }
        }

        // ---- softmax (unnormalized) ----
        bool edge = (kt == 0) || (kt >= 2 * qt);
        int colb = kt * 64 + 2 * (lane & 3);
#pragma unroll
        for (int n = 0; n < 8; n++) {
            float e0 = ex2f(sc[n][0] * Cc);
            float e1 = ex2f(sc[n][1] * Cc);
            float e2 = ex2f(sc[n][2] * Cc);
            float e3 = ex2f(sc[n][3] * Cc);
            if (edge) {
                int c0 = colb + 8 * n, c1 = c0 + 1;
                bool k00 = (c0 <= row0) && (c0 >= PREFIX || row0 < PREFIX);
                bool k01 = (c1 <= row0) && (c1 >= PREFIX || row0 < PREFIX);
                bool k10 = (c0 <= row1) && (c0 >= PREFIX || row1 < PREFIX);
                bool k11 = (c1 <= row1) && (c1 >= PREFIX || row1 < PREFIX);
                e0 = k00 ? e0 : 0.f;
                e1 = k01 ? e1 : 0.f;
                e2 = k10 ? e2 : 0.f;
                e3 = k11 ? e3 : 0.f;
            }
            sc[n][0] = e0; sc[n][1] = e1; sc[n][2] = e2; sc[n][3] = e3;
            lsum0 += e0 + e1;
            lsum1 += e2 + e3;
        }

        // ---- O += P V ----
#pragma unroll
        for (int t = 0; t < 4; t++) {
            uint32_t ph[4], pl[4];
            {
                float* cA = sc[2 * t];
                float* cB = sc[2 * t + 1];
                uint32_t a0 = f2u(cA[0]), a1 = f2u(cA[1]);
                uint32_t a2 = f2u(cA[2]), a3 = f2u(cA[3]);
                uint32_t b0 = f2u(cB[0]), b1 = f2u(cB[1]);
                uint32_t b2 = f2u(cB[2]), b3 = f2u(cB[3]);
                ph[0] = prmt_hi16(a0, a1);
                ph[1] = prmt_hi16(a2, a3);
                ph[2] = prmt_hi16(b0, b1);
                ph[3] = prmt_hi16(b2, b3);
                pl[0] = cvt_bf16x2(cA[0] - __uint_as_float(a0 & 0xffff0000u),
                                   cA[1] - __uint_as_float(a1 & 0xffff0000u));
                pl[1] = cvt_bf16x2(cA[2] - __uint_as_float(a2 & 0xffff0000u),
                                   cA[3] - __uint_as_float(a3 & 0xffff0000u));
                pl[2] = cvt_bf16x2(cB[0] - __uint_as_float(b0 & 0xffff0000u),
                                   cB[1] - __uint_as_float(b1 & 0xffff0000u));
                pl[3] = cvt_bf16x2(cB[2] - __uint_as_float(b2 & 0xffff0000u),
                                   cB[3] - __uint_as_float(b3 & 0xffff0000u));
            }
            int key = t * 16 + (lane & 7) + ((lane & 8) ? 8 : 0);
#pragma unroll
            for (int dpp = 0; dpp < 2; dpp++) {
                uint32_t col0 = (uint32_t)((2 * dpp) * 32 + ((lane & 16) ? 16 : 0));
                uint32_t off0 = swz128((uint32_t)key * 128u + col0);
                uint32_t off1 = swz128((uint32_t)key * 128u + col0 + 32u);
                uint32_t h00, h01, h02, h03, l00, l01, l02, l03;
                uint32_t h10, h11, h12, h13, l10, l11, l12, l13;
                ldsm4t(h00, h01, h02, h03, kvb + 16384u + off0);
                ldsm4t(l00, l01, l02, l03, kvb + 24576u + off0);
                ldsm4t(h10, h11, h12, h13, kvb + 16384u + off1);
                ldsm4t(l10, l11, l12, l13, kvb + 24576u + off1);
                float* o0 = oc[4 * dpp + 0];
                float* o1 = oc[4 * dpp + 1];
                float* o2 = oc[4 * dpp + 2];
                float* o3 = oc[4 * dpp + 3];
                mma_bf16(o0, ph, h00, h01);
                mma_bf16(o1, ph, h02, h03);
                mma_bf16(o2, ph, h10, h11);
                mma_bf16(o3, ph, h12, h13);
                mma_bf16(o0, ph, l00, l01);
                mma_bf16(o1, ph, l02, l03);
                mma_bf16(o2, ph, l10, l11);
                mma_bf16(o3, ph, l12, l13);
                mma_bf16(o0, pl, h00, h01);
                mma_bf16(o1, pl, h02, h03);
                mma_bf16(o2, pl, h10, h11);
                mma_bf16(o3, pl, h12, h13);
            }
        }
        __syncthreads();
    }
#undef ISSUE_KV

    // lane reduction of lsum
    lsum0 += __shfl_xor_sync(0xffffffffu, lsum0, 1);
    lsum0 += __shfl_xor_sync(0xffffffffu, lsum0, 2);
    lsum1 += __shfl_xor_sync(0xffffffffu, lsum1, 1);
    lsum1 += __shfl_xor_sync(0xffffffffu, lsum1, 2);
    float inv0 = 1.f / lsum0, inv1 = 1.f / lsum1;

    // store ctx as bf16 hi/lo
    int b = bh >> 3, h = bh & 7;
    size_t r0base = (size_t)(b * L_ + row0) * HIDDEN + h * 64;
    size_t r1base = (size_t)(b * L_ + row1) * HIDDEN + h * 64;
#pragma unroll
    for (int n = 0; n < 8; n++) {
        int d = 8 * n + 2 * (lane & 3);
        float v0 = oc[n][0] * inv0, v1 = oc[n][1] * inv0;
        float v2 = oc[n][2] * inv1, v3 = oc[n][3] * inv1;
        uint32_t u0 = f2u(v0), u1 = f2u(v1), u2 = f2u(v2), u3 = f2u(v3);
        *(uint32_t*)(gctx_hi + r0base + d) = prmt_hi16(u0, u1);
        *(uint32_t*)(gctx_lo + r0base + d) =
            cvt_bf16x2(v0 - __uint_as_float(u0 & 0xffff0000u),
                       v1 - __uint_as_float(u1 & 0xffff0000u));
        *(uint32_t*)(gctx_hi + r1base + d) = prmt_hi16(u2, u3);
        *(uint32_t*)(gctx_lo + r1base + d) =
            cvt_bf16x2(v2 - __uint_as_float(u2 & 0xffff0000u),
                       v3 - __uint_as_float(u3 & 0xffff0000u));
    }
}

// ============================================================
extern "C" void kernel_launch(void* const* d_in, const int* in_sizes, int n_in,
                              void* d_out, int out_size)
{
    const float* x     = (const float*)d_in[0];
    const float* w_in  = (const float*)d_in[1];
    const float* b_in  = (const float*)d_in[2];
    const float* w_out = (const float*)d_in[3];
    const float* b_out = (const float*)d_in[4];
    float* out = (float*)d_out;

    conv_x_kernel<<<(M_ROWS * HIDDEN / 4) / 256, 256>>>(x);
    conv_wT_kernel<<<dim3(3 * HIDDEN / 32, HIDDEN / 32), 256>>>(w_in, HIDDEN, 3 * HIDDEN, 0);
    conv_wT_kernel<<<dim3(HIDDEN / 32, HIDDEN / 32), 256>>>(w_out, HIDDEN, HIDDEN, 1);

    cudaFuncSetAttribute(gemm_bf16_kernel<0>,
                         cudaFuncAttributeMaxDynamicSharedMemorySize, 2 * GSTAGE);
    gemm_bf16_kernel<0><<<dim3(24, 64), 256, 2 * GSTAGE>>>(b_in, nullptr);

    cudaFuncSetAttribute(attn_mma_kernel,
                         cudaFuncAttributeMaxDynamicSharedMemorySize, ATTN_SMEM);
    attn_mma_kernel<<<dim3(16, 32), 256, ATTN_SMEM>>>();

    cudaFuncSetAttribute(gemm_bf16_kernel<1>,
                         cudaFuncAttributeMaxDynamicSharedMemorySize, 2 * GSTAGE);
    gemm_bf16_kernel<1><<<dim3(8, 64), 256, 2 * GSTAGE>>>(b_out, out);
}

// round 10
// speedup vs baseline: 1.0995x; 1.0135x over previous
#include <cuda_runtime.h>
#include <cstdint>

typedef unsigned long long ull;

#define B_      2
#define L_      4096
#define HIDDEN  512
#define HEADS   8
#define HD      64
#define PREFIX  1
#define M_ROWS  (B_ * L_)        // 8192

// ---- bf16 hi/lo split storage (allocation-free: __device__ globals) ----
__device__ __align__(16) uint16_t gx_hi[M_ROWS * HIDDEN],  gx_lo[M_ROWS * HIDDEN];
__device__ __align__(16) uint16_t gwi_hi[3 * HIDDEN * HIDDEN], gwi_lo[3 * HIDDEN * HIDDEN];
__device__ __align__(16) uint16_t gwo_hi[HIDDEN * HIDDEN], gwo_lo[HIDDEN * HIDDEN];
__device__ __align__(16) uint16_t gq_hi[M_ROWS * HIDDEN],  gq_lo[M_ROWS * HIDDEN];
__device__ __align__(16) uint16_t gk_hi[M_ROWS * HIDDEN],  gk_lo[M_ROWS * HIDDEN];
__device__ __align__(16) uint16_t gv_hi[M_ROWS * HIDDEN],  gv_lo[M_ROWS * HIDDEN];
__device__ __align__(16) uint16_t gctx_hi[M_ROWS * HIDDEN], gctx_lo[M_ROWS * HIDDEN];

// ============================================================
// helpers
// ============================================================
__device__ __forceinline__ uint32_t smem_u32(const void* p) {
    uint32_t a;
    asm("{ .reg .u64 t; cvta.to.shared.u64 t, %1; cvt.u32.u64 %0, t; }" : "=r"(a) : "l"(p));
    return a;
}
__device__ __forceinline__ uint32_t f2u(float x) { return __float_as_uint(x); }
__device__ __forceinline__ uint32_t prmt_hi16(uint32_t a, uint32_t b) {
    uint32_t r; asm("prmt.b32 %0,%1,%2,0x7632;" : "=r"(r) : "r"(a), "r"(b)); return r;
}
__device__ __forceinline__ uint32_t cvt_bf16x2(float lo, float hi) {
    uint32_t r; asm("cvt.rn.bf16x2.f32 %0,%1,%2;" : "=r"(r) : "f"(hi), "f"(lo)); return r;
}
__device__ __forceinline__ uint16_t bf16_rn(float x) {
    uint16_t u; asm("cvt.rn.bf16.f32 %0,%1;" : "=h"(u) : "f"(x)); return u;
}
__device__ __forceinline__ float ex2f(float x) {
    float r; asm("ex2.approx.f32 %0,%1;" : "=f"(r) : "f"(x)); return r;
}
__device__ __forceinline__ uint32_t swz128(uint32_t o) { return o ^ ((o >> 3) & 0x70u); }
__device__ __forceinline__ uint32_t swz64(uint32_t o)  { return o ^ ((o >> 3) & 0x30u); }

__device__ __forceinline__ void cp16(uint32_t dst, const void* src) {
    asm volatile("cp.async.cg.shared.global [%0], [%1], 16;" :: "r"(dst), "l"(src) : "memory");
}
__device__ __forceinline__ void cp_commit() {
    asm volatile("cp.async.commit_group;" ::: "memory");
}
template <int N> __device__ __forceinline__ void cp_wait() {
    asm volatile("cp.async.wait_group %0;" :: "n"(N) : "memory");
}

__device__ __forceinline__ void ldsm4(uint32_t& r0, uint32_t& r1, uint32_t& r2, uint32_t& r3,
                                      uint32_t addr) {
    asm volatile("ldmatrix.sync.aligned.m8n8.x4.shared.b16 {%0,%1,%2,%3}, [%4];"
                 : "=r"(r0), "=r"(r1), "=r"(r2), "=r"(r3) : "r"(addr));
}
__device__ __forceinline__ void ldsm4t(uint32_t& r0, uint32_t& r1, uint32_t& r2, uint32_t& r3,
                                       uint32_t addr) {
    asm volatile("ldmatrix.sync.aligned.m8n8.x4.trans.shared.b16 {%0,%1,%2,%3}, [%4];"
                 : "=r"(r0), "=r"(r1), "=r"(r2), "=r"(r3) : "r"(addr));
}
__device__ __forceinline__ void mma_bf16(float* c, const uint32_t* a, uint32_t b0, uint32_t b1) {
    asm volatile(
        "mma.sync.aligned.m16n8k16.row.col.f32.bf16.bf16.f32 "
        "{%0,%1,%2,%3},{%4,%5,%6,%7},{%8,%9},{%0,%1,%2,%3};"
        : "+f"(c[0]), "+f"(c[1]), "+f"(c[2]), "+f"(c[3])
        : "r"(a[0]), "r"(a[1]), "r"(a[2]), "r"(a[3]), "r"(b0), "r"(b1));
}

// ============================================================
// conversion kernels: fp32 -> bf16 hi/lo split
// ============================================================
__global__ __launch_bounds__(256) void conv_x_kernel(const float* __restrict__ x)
{
    size_t gid = (size_t)blockIdx.x * 256 + threadIdx.x;
    size_t i = gid * 4;
    float4 v = *(const float4*)(x + i);
    uint32_t bx = f2u(v.x), by = f2u(v.y), bz = f2u(v.z), bw = f2u(v.w);
    uint2 H, Lw;
    H.x = prmt_hi16(bx, by);
    H.y = prmt_hi16(bz, bw);
    Lw.x = cvt_bf16x2(v.x - __uint_as_float(bx & 0xffff0000u),
                      v.y - __uint_as_float(by & 0xffff0000u));
    Lw.y = cvt_bf16x2(v.z - __uint_as_float(bz & 0xffff0000u),
                      v.w - __uint_as_float(bw & 0xffff0000u));
    *(uint2*)(gx_hi + i) = H;
    *(uint2*)(gx_lo + i) = Lw;
}

__global__ __launch_bounds__(256) void conv_wT_kernel(const float* __restrict__ w,
                                                      int K, int N, int which)
{
    __shared__ float t[32][33];
    uint16_t* dh = which ? gwo_hi : gwi_hi;
    uint16_t* dl = which ? gwo_lo : gwi_lo;
    int n0 = blockIdx.x * 32, k0 = blockIdx.y * 32;
    int tx = threadIdx.x & 31, ty = threadIdx.x >> 5;
#pragma unroll
    for (int i = 0; i < 4; i++)
        t[ty + 8 * i][tx] = w[(size_t)(k0 + ty + 8 * i) * N + n0 + tx];
    __syncthreads();
#pragma unroll
    for (int i = 0; i < 4; i++) {
        int nn = ty + 8 * i;
        float v = t[tx][nn];
        uint32_t b = f2u(v);
        size_t idx = (size_t)(n0 + nn) * K + k0 + tx;
        dh[idx] = (uint16_t)(b >> 16);
        dl[idx] = bf16_rn(v - __uint_as_float(b & 0xffff0000u));
    }
}

// ============================================================
// GEMM bf16x3: CTA tile 128x128, 256 thr, warp tile 32x64,
// k-chunk 32, 3-stage cp.async pipeline, SW64 swizzle, 2 CTA/SM.
// Stage (32KB): {AHI 0, ALO 8K, BHI 16K, BLO 24K}; stride 32768.
// ============================================================
#define GSTAGE 32768u

template <int MODE>
__global__ __launch_bounds__(256, 2) void gemm_bf16_kernel(
    const float* __restrict__ bias, float* __restrict__ Cout)
{
    extern __shared__ char smp[];
    const uint32_t sbase = smem_u32(smp);
    int tid = threadIdx.x;
    int lane = tid & 31, w = tid >> 5;
    int wm = w >> 1, wn = w & 1;     // 4 x 2 warp grid, warp tile 32x64
    int bm = blockIdx.y, bn = blockIdx.x;

    const uint16_t* Ahi = (MODE == 0) ? gx_hi : gctx_hi;
    const uint16_t* Alo = (MODE == 0) ? gx_lo : gctx_lo;
    const uint16_t* Bhi = (MODE == 0) ? gwi_hi : gwo_hi;
    const uint16_t* Blo = (MODE == 0) ? gwi_lo : gwo_lo;

    // loaders: 2 thr/row (64B row), 2 16B-groups per thread
    int r = tid >> 1, g0 = (tid & 1) * 2;
    size_t aoff = (size_t)(bm * 128 + r) * HIDDEN;
    size_t boff = (size_t)(bn * 128 + r) * HIDDEN;

    float acc[2][8][4];
#pragma unroll
    for (int i = 0; i < 2; i++)
#pragma unroll
        for (int j = 0; j < 8; j++)
#pragma unroll
            for (int e = 0; e < 4; e++) acc[i][j][e] = 0.f;

#define ISSUE_CHUNK(kc, buf) do {                                               \
        uint32_t dst = sbase + (uint32_t)(buf) * GSTAGE;                         \
        const uint16_t* ah = Ahi + aoff + (kc) * 32;                             \
        const uint16_t* al = Alo + aoff + (kc) * 32;                             \
        const uint16_t* bh = Bhi + boff + (kc) * 32;                             \
        const uint16_t* bl = Blo + boff + (kc) * 32;                             \
        _Pragma("unroll")                                                        \
        for (int i = 0; i < 2; i++) {                                            \
            uint32_t so = swz64((uint32_t)r * 64u + (uint32_t)(g0 + i) * 16u);   \
            cp16(dst + so,           ah + (g0 + i) * 8);                         \
            cp16(dst + 8192u  + so,  al + (g0 + i) * 8);                         \
            cp16(dst + 16384u + so,  bh + (g0 + i) * 8);                         \
            cp16(dst + 24576u + so,  bl + (g0 + i) * 8);                         \
        }                                                                        \
        cp_commit();                                                             \
    } while (0)

    ISSUE_CHUNK(0, 0);
    ISSUE_CHUNK(1, 1);

    const int NK = HIDDEN / 32;   // 16 chunks
    int rb = 0;
    for (int kc = 0; kc < NK; kc++) {
        if (kc + 2 < NK) {
            int wb = rb + 2; if (wb >= 3) wb -= 3;
            ISSUE_CHUNK(kc + 2, wb);
            cp_wait<2>();
        } else if (kc + 1 < NK) {
            cp_wait<1>();
        } else {
            cp_wait<0>();
        }
        __syncthreads();

        uint32_t abase = sbase + (uint32_t)rb * GSTAGE;
        uint32_t bbase = abase + 16384u;
#pragma unroll
        for (int ks = 0; ks < 2; ks++) {
            uint32_t ah[2][4], al[2][4];
#pragma unroll
            for (int mi = 0; mi < 2; mi++) {
                uint32_t off = swz64((uint32_t)(wm * 32 + mi * 16 + (lane & 15)) * 64u
                                     + (uint32_t)(ks * 32 + ((lane & 16) ? 16 : 0)));
                ldsm4(ah[mi][0], ah[mi][1], ah[mi][2], ah[mi][3], abase + off);
                ldsm4(al[mi][0], al[mi][1], al[mi][2], al[mi][3], abase + 8192u + off);
            }
#pragma unroll
            for (int np = 0; np < 4; np++) {
                uint32_t boffs = swz64((uint32_t)(wn * 64 + np * 16 + (lane & 7)
                                                  + ((lane & 16) ? 8 : 0)) * 64u
                                       + (uint32_t)(ks * 32 + ((lane & 8) ? 16 : 0)));
                uint32_t bh0, bh1, bh2, bh3, bl0, bl1, bl2, bl3;
                ldsm4(bh0, bh1, bh2, bh3, bbase + boffs);
                ldsm4(bl0, bl1, bl2, bl3, bbase + 8192u + boffs);
#pragma unroll
                for (int mi = 0; mi < 2; mi++) {
                    mma_bf16(acc[mi][2 * np],     ah[mi], bh0, bh1);
                    mma_bf16(acc[mi][2 * np + 1], ah[mi], bh2, bh3);
                }
#pragma unroll
                for (int mi = 0; mi < 2; mi++) {
                    mma_bf16(acc[mi][2 * np],     ah[mi], bl0, bl1);
                    mma_bf16(acc[mi][2 * np + 1], ah[mi], bl2, bl3);
                }
#pragma unroll
                for (int mi = 0; mi < 2; mi++) {
                    mma_bf16(acc[mi][2 * np],     al[mi], bh0, bh1);
                    mma_bf16(acc[mi][2 * np + 1], al[mi], bh2, bh3);
                }
            }
        }
        __syncthreads();
        rb = rb + 1; if (rb == 3) rb = 0;
    }
#undef ISSUE_CHUNK

    // ---- epilogue ----
#pragma unroll
    for (int mi = 0; mi < 2; mi++) {
        int r0 = bm * 128 + wm * 32 + mi * 16 + (lane >> 2);
#pragma unroll
        for (int nj = 0; nj < 8; nj++) {
            int c0 = bn * 128 + wn * 64 + nj * 8 + 2 * (lane & 3);
            float bb0 = __ldg(bias + c0), bb1 = __ldg(bias + c0 + 1);
            float v0 = acc[mi][nj][0] + bb0, v1 = acc[mi][nj][1] + bb1;
            float v2 = acc[mi][nj][2] + bb0, v3 = acc[mi][nj][3] + bb1;
            if (MODE == 0) {
                int which = c0 >> 9, h = (c0 >> 6) & 7, d = c0 & 63;
                uint16_t* dh = (which == 0) ? gq_hi : (which == 1) ? gk_hi : gv_hi;
                uint16_t* dl = (which == 0) ? gq_lo : (which == 1) ? gk_lo : gv_lo;
                int b = r0 >> 12;
                size_t base0 = ((size_t)((b * 8 + h) * L_ + (r0 & 4095))) * 64 + d;
                size_t base1 = base0 + 8 * 64;
                uint32_t u0 = f2u(v0), u1 = f2u(v1), u2 = f2u(v2), u3 = f2u(v3);
                *(uint32_t*)(dh + base0) = prmt_hi16(u0, u1);
                *(uint32_t*)(dl + base0) =
                    cvt_bf16x2(v0 - __uint_as_float(u0 & 0xffff0000u),
                               v1 - __uint_as_float(u1 & 0xffff0000u));
                *(uint32_t*)(dh + base1) = prmt_hi16(u2, u3);
                *(uint32_t*)(dl + base1) =
                    cvt_bf16x2(v2 - __uint_as_float(u2 & 0xffff0000u),
                               v3 - __uint_as_float(u3 & 0xffff0000u));
            } else {
                *(float2*)(Cout + (size_t)r0 * HIDDEN + c0) = make_float2(v0, v1);
                *(float2*)(Cout + (size_t)(r0 + 8) * HIDDEN + c0) = make_float2(v2, v3);
            }
        }
    }
}

// ============================================================
// Attention SMEM: Q 32KB; K/V double buffer (2 x 32KB). 96KB.
// ============================================================
#define SQHI 0u
#define SQLO 16384u
#define SKV0 32768u
#define ATTN_SMEM 98304

// 2 CTAs/SM: <=128 regs. Q-lo fragments loaded on demand.
__global__ __launch_bounds__(256, 2) void attn_mma_kernel()
{
    extern __shared__ char smp[];
    const uint32_t sbase = smem_u32(smp);
    int tid = threadIdx.x;
    int w = tid >> 5, lane = tid & 31;

    int bh = blockIdx.x;                            // b*8 + h
    int qt = (int)gridDim.y - 1 - (int)blockIdx.y;  // heavy tiles first
    int nkt = 2 * qt + 2;                           // 64-key tiles

    int ct = tid & 127;
    int rr = ct >> 1, g0 = (ct & 1) * 4;
    const uint16_t* srch = (tid < 128) ? gk_hi : gv_hi;
    const uint16_t* srcl = (tid < 128) ? gk_lo : gv_lo;
    uint32_t dsel = (tid < 128) ? 0u : 16384u;

#define ISSUE_KV(kt, buf) do {                                                   \
        uint32_t dst = sbase + SKV0 + (uint32_t)(buf) * 32768u + dsel;           \
        const uint16_t* sh = srch + ((size_t)bh * L_ + (size_t)(kt) * 64 + rr) * 64; \
        const uint16_t* sl = srcl + ((size_t)bh * L_ + (size_t)(kt) * 64 + rr) * 64; \
        _Pragma("unroll")                                                        \
        for (int i = 0; i < 4; i++) {                                            \
            uint32_t so = swz128((uint32_t)rr * 128u + (uint32_t)(g0 + i) * 16u);\
            cp16(dst + so,          sh + (g0 + i) * 8);                          \
            cp16(dst + 8192u + so,  sl + (g0 + i) * 8);                          \
        }                                                                        \
        cp_commit();                                                             \
    } while (0)

    // Prologue: Q tile copy + first K/V issue
    {
        const uint4* qh4 = (const uint4*)(gq_hi + ((size_t)bh * L_ + (size_t)qt * 128 + (tid >> 1)) * 64);
        const uint4* ql4 = (const uint4*)(gq_lo + ((size_t)bh * L_ + (size_t)qt * 128 + (tid >> 1)) * 64);
        int qg0 = (tid & 1) * 4;
#pragma unroll
        for (int i = 0; i < 4; i++) {
            uint32_t so = swz128((uint32_t)(tid >> 1) * 128u + (uint32_t)(qg0 + i) * 16u);
            *(uint4*)(smp + SQHI + so) = qh4[qg0 + i];
            *(uint4*)(smp + SQLO + so) = ql4[qg0 + i];
        }
    }
    ISSUE_KV(0, 0);
    __syncthreads();

    int arow = 16 * w + (lane & 15);
    uint32_t qh[4][4];
    uint32_t qloff[4];
    {
#pragma unroll
        for (int ks = 0; ks < 4; ks++) {
            uint32_t off = swz128((uint32_t)arow * 128u
                                  + (uint32_t)(ks * 32 + ((lane & 16) ? 16 : 0)));
            ldsm4(qh[ks][0], qh[ks][1], qh[ks][2], qh[ks][3], sbase + SQHI + off);
            qloff[ks] = sbase + SQLO + off;
        }
    }

    float oc[8][4];
#pragma unroll
    for (int n = 0; n < 8; n++)
#pragma unroll
        for (int j = 0; j < 4; j++) oc[n][j] = 0.f;
    float lsum0 = 0.f, lsum1 = 0.f;

    const float Cc = 0.18033688011112042f;  // (1/8) * log2(e)
    int row0 = qt * 128 + 16 * w + (lane >> 2);
    int row1 = row0 + 8;

    for (int kt = 0; kt < nkt; ++kt) {
        if (kt + 1 < nkt) {
            ISSUE_KV(kt + 1, (kt + 1) & 1);
            cp_wait<1>();
        } else {
            cp_wait<0>();
        }
        __syncthreads();

        uint32_t kvb = sbase + SKV0 + (uint32_t)(kt & 1) * 32768u;

        // ---- S = Q K^T ----
        float sc[8][4];
#pragma unroll
        for (int n = 0; n < 8; n++)
#pragma unroll
            for (int j = 0; j < 4; j++) sc[n][j] = 0.f;

#pragma unroll
        for (int ks = 0; ks < 4; ks++) {
            uint32_t ql[4];
            ldsm4(ql[0], ql[1], ql[2], ql[3], qloff[ks]);
#pragma unroll
            for (int npp = 0; npp < 2; npp++) {
                int key0 = (2 * npp) * 16 + (lane & 7) + ((lane & 16) ? 8 : 0);
                uint32_t col = (uint32_t)(ks * 32 + ((lane & 8) ? 16 : 0));
                uint32_t off0 = swz128((uint32_t)key0 * 128u + col);
                uint32_t off1 = swz128((uint32_t)(key0 + 16) * 128u + col);
                uint32_t h00, h01, h02, h03, l00, l01, l02, l03;
                uint32_t h10, h11, h12, h13, l10, l11, l12, l13;
                ldsm4(h00, h01, h02, h03, kvb + off0);
                ldsm4(l00, l01, l02, l03, kvb + 8192u + off0);
                ldsm4(h10, h11, h12, h13, kvb + off1);
                ldsm4(l10, l11, l12, l13, kvb + 8192u + off1);
                float* s0 = sc[4 * npp + 0];
                float* s1 = sc[4 * npp + 1];
                float* s2 = sc[4 * npp + 2];
                float* s3 = sc[4 * npp + 3];
                mma_bf16(s0, qh[ks], h00, h01);
                mma_bf16(s1, qh[ks], h02, h03);
                mma_bf16(s2, qh[ks], h10, h11);
                mma_bf16(s3, qh[ks], h12, h13);
                mma_bf16(s0, qh[ks], l00, l01);
                mma_bf16(s1, qh[ks], l02, l03);
                mma_bf16(s2, qh[ks], l10, l11);
                mma_bf16(s3, qh[ks], l12, l13);
                mma_bf16(s0, ql, h00, h01);
                mma_bf16(s1, ql, h02, h03);
                mma_bf16(s2, ql, h10, h11);
                mma_bf16(s3, ql, h12, h13);
            }
        }

        // ---- softmax (unnormalized) ----
        bool edge = (kt == 0) || (kt >= 2 * qt);
        int colb = kt * 64 + 2 * (lane & 3);
#pragma unroll
        for (int n = 0; n < 8; n++) {
            float e0 = ex2f(sc[n][0] * Cc);
            float e1 = ex2f(sc[n][1] * Cc);
            float e2 = ex2f(sc[n][2] * Cc);
            float e3 = ex2f(sc[n][3] * Cc);
            if (edge) {
                int c0 = colb + 8 * n, c1 = c0 + 1;
                bool k00 = (c0 <= row0) && (c0 >= PREFIX || row0 < PREFIX);
                bool k01 = (c1 <= row0) && (c1 >= PREFIX || row0 < PREFIX);
                bool k10 = (c0 <= row1) && (c0 >= PREFIX || row1 < PREFIX);
                bool k11 = (c1 <= row1) && (c1 >= PREFIX || row1 < PREFIX);
                e0 = k00 ? e0 : 0.f;
                e1 = k01 ? e1 : 0.f;
                e2 = k10 ? e2 : 0.f;
                e3 = k11 ? e3 : 0.f;
            }
            sc[n][0] = e0; sc[n][1] = e1; sc[n][2] = e2; sc[n][3] = e3;
            lsum0 += e0 + e1;
            lsum1 += e2 + e3;
        }

        // ---- O += P V ----
#pragma unroll
        for (int t = 0; t < 4; t++) {
            uint32_t ph[4], pl[4];
            {
                float* cA = sc[2 * t];
                float* cB = sc[2 * t + 1];
                uint32_t a0 = f2u(cA[0]), a1 = f2u(cA[1]);
                uint32_t a2 = f2u(cA[2]), a3 = f2u(cA[3]);
                uint32_t b0 = f2u(cB[0]), b1 = f2u(cB[1]);
                uint32_t b2 = f2u(cB[2]), b3 = f2u(cB[3]);
                ph[0] = prmt_hi16(a0, a1);
                ph[1] = prmt_hi16(a2, a3);
                ph[2] = prmt_hi16(b0, b1);
                ph[3] = prmt_hi16(b2, b3);
                pl[0] = cvt_bf16x2(cA[0] - __uint_as_float(a0 & 0xffff0000u),
                                   cA[1] - __uint_as_float(a1 & 0xffff0000u));
                pl[1] = cvt_bf16x2(cA[2] - __uint_as_float(a2 & 0xffff0000u),
                                   cA[3] - __uint_as_float(a3 & 0xffff0000u));
                pl[2] = cvt_bf16x2(cB[0] - __uint_as_float(b0 & 0xffff0000u),
                                   cB[1] - __uint_as_float(b1 & 0xffff0000u));
                pl[3] = cvt_bf16x2(cB[2] - __uint_as_float(b2 & 0xffff0000u),
                                   cB[3] - __uint_as_float(b3 & 0xffff0000u));
            }
            int key = t * 16 + (lane & 7) + ((lane & 8) ? 8 : 0);
#pragma unroll
            for (int dpp = 0; dpp < 2; dpp++) {
                uint32_t col0 = (uint32_t)((2 * dpp) * 32 + ((lane & 16) ? 16 : 0));
                uint32_t off0 = swz128((uint32_t)key * 128u + col0);
                uint32_t off1 = swz128((uint32_t)key * 128u + col0 + 32u);
                uint32_t h00, h01, h02, h03, l00, l01, l02, l03;
                uint32_t h10, h11, h12, h13, l10, l11, l12, l13;
                ldsm4t(h00, h01, h02, h03, kvb + 16384u + off0);
                ldsm4t(l00, l01, l02, l03, kvb + 24576u + off0);
                ldsm4t(h10, h11, h12, h13, kvb + 16384u + off1);
                ldsm4t(l10, l11, l12, l13, kvb + 24576u + off1);
                float* o0 = oc[4 * dpp + 0];
                float* o1 = oc[4 * dpp + 1];
                float* o2 = oc[4 * dpp + 2];
                float* o3 = oc[4 * dpp + 3];
                mma_bf16(o0, ph, h00, h01);
                mma_bf16(o1, ph, h02, h03);
                mma_bf16(o2, ph, h10, h11);
                mma_bf16(o3, ph, h12, h13);
                mma_bf16(o0, ph, l00, l01);
                mma_bf16(o1, ph, l02, l03);
                mma_bf16(o2, ph, l10, l11);
                mma_bf16(o3, ph, l12, l13);
                mma_bf16(o0, pl, h00, h01);
                mma_bf16(o1, pl, h02, h03);
                mma_bf16(o2, pl, h10, h11);
                mma_bf16(o3, pl, h12, h13);
            }
        }
        __syncthreads();
    }
#undef ISSUE_KV

    // lane reduction of lsum
    lsum0 += __shfl_xor_sync(0xffffffffu, lsum0, 1);
    lsum0 += __shfl_xor_sync(0xffffffffu, lsum0, 2);
    lsum1 += __shfl_xor_sync(0xffffffffu, lsum1, 1);
    lsum1 += __shfl_xor_sync(0xffffffffu, lsum1, 2);
    float inv0 = 1.f / lsum0, inv1 = 1.f / lsum1;

    // store ctx as bf16 hi/lo
    int b = bh >> 3, h = bh & 7;
    size_t r0base = (size_t)(b * L_ + row0) * HIDDEN + h * 64;
    size_t r1base = (size_t)(b * L_ + row1) * HIDDEN + h * 64;
#pragma unroll
    for (int n = 0; n < 8; n++) {
        int d = 8 * n + 2 * (lane & 3);
        float v0 = oc[n][0] * inv0, v1 = oc[n][1] * inv0;
        float v2 = oc[n][2] * inv1, v3 = oc[n][3] * inv1;
        uint32_t u0 = f2u(v0), u1 = f2u(v1), u2 = f2u(v2), u3 = f2u(v3);
        *(uint32_t*)(gctx_hi + r0base + d) = prmt_hi16(u0, u1);
        *(uint32_t*)(gctx_lo + r0base + d) =
            cvt_bf16x2(v0 - __uint_as_float(u0 & 0xffff0000u),
                       v1 - __uint_as_float(u1 & 0xffff0000u));
        *(uint32_t*)(gctx_hi + r1base + d) = prmt_hi16(u2, u3);
        *(uint32_t*)(gctx_lo + r1base + d) =
            cvt_bf16x2(v2 - __uint_as_float(u2 & 0xffff0000u),
                       v3 - __uint_as_float(u3 & 0xffff0000u));
    }
}

// ============================================================
extern "C" void kernel_launch(void* const* d_in, const int* in_sizes, int n_in,
                              void* d_out, int out_size)
{
    const float* x     = (const float*)d_in[0];
    const float* w_in  = (const float*)d_in[1];
    const float* b_in  = (const float*)d_in[2];
    const float* w_out = (const float*)d_in[3];
    const float* b_out = (const float*)d_in[4];
    float* out = (float*)d_out;

    conv_x_kernel<<<(M_ROWS * HIDDEN / 4) / 256, 256>>>(x);
    conv_wT_kernel<<<dim3(3 * HIDDEN / 32, HIDDEN / 32), 256>>>(w_in, HIDDEN, 3 * HIDDEN, 0);
    conv_wT_kernel<<<dim3(HIDDEN / 32, HIDDEN / 32), 256>>>(w_out, HIDDEN, HIDDEN, 1);

    cudaFuncSetAttribute(gemm_bf16_kernel<0>,
                         cudaFuncAttributeMaxDynamicSharedMemorySize, 3 * GSTAGE);
    gemm_bf16_kernel<0><<<dim3(12, 64), 256, 3 * GSTAGE>>>(b_in, nullptr);

    cudaFuncSetAttribute(attn_mma_kernel,
                         cudaFuncAttributeMaxDynamicSharedMemorySize, ATTN_SMEM);
    attn_mma_kernel<<<dim3(16, 32), 256, ATTN_SMEM>>>();

    cudaFuncSetAttribute(gemm_bf16_kernel<1>,
                         cudaFuncAttributeMaxDynamicSharedMemorySize, 3 * GSTAGE);
    gemm_bf16_kernel<1><<<dim3(4, 64), 256, 3 * GSTAGE>>>(b_out, out);
}

// round 11
// speedup vs baseline: 1.6722x; 1.5209x over previous
#include <cuda_runtime.h>
#include <cstdint>

typedef unsigned long long ull;

#define B_      2
#define L_      4096
#define HIDDEN  512
#define HEADS   8
#define HD      64
#define PREFIX  1
#define M_ROWS  (B_ * L_)        // 8192

// ---- split/packed storage (allocation-free: __device__ globals) ----
__device__ __align__(16) uint16_t gx_hi[M_ROWS * HIDDEN],  gx_lo[M_ROWS * HIDDEN];
__device__ __align__(16) uint16_t gwi_hi[3 * HIDDEN * HIDDEN], gwi_lo[3 * HIDDEN * HIDDEN];
__device__ __align__(16) uint16_t gwo_hi[HIDDEN * HIDDEN], gwo_lo[HIDDEN * HIDDEN];
__device__ __align__(16) uint16_t gq_f16[M_ROWS * HIDDEN];   // fp16 single
__device__ __align__(16) uint16_t gk_f16[M_ROWS * HIDDEN];
__device__ __align__(16) uint16_t gv_f16[M_ROWS * HIDDEN];
__device__ __align__(16) uint16_t gctx_hi[M_ROWS * HIDDEN], gctx_lo[M_ROWS * HIDDEN];

// ============================================================
// helpers
// ============================================================
__device__ __forceinline__ uint32_t smem_u32(const void* p) {
    uint32_t a;
    asm("{ .reg .u64 t; cvta.to.shared.u64 t, %1; cvt.u32.u64 %0, t; }" : "=r"(a) : "l"(p));
    return a;
}
__device__ __forceinline__ uint32_t f2u(float x) { return __float_as_uint(x); }
__device__ __forceinline__ uint32_t prmt_hi16(uint32_t a, uint32_t b) {
    uint32_t r; asm("prmt.b32 %0,%1,%2,0x7632;" : "=r"(r) : "r"(a), "r"(b)); return r;
}
__device__ __forceinline__ uint32_t cvt_bf16x2(float lo, float hi) {
    uint32_t r; asm("cvt.rn.bf16x2.f32 %0,%1,%2;" : "=r"(r) : "f"(hi), "f"(lo)); return r;
}
// pack {lo, hi} floats into f16x2 (first arg -> low half)
__device__ __forceinline__ uint32_t cvt_f16x2(float lo, float hi) {
    uint32_t r; asm("cvt.rn.f16x2.f32 %0,%1,%2;" : "=r"(r) : "f"(hi), "f"(lo)); return r;
}
__device__ __forceinline__ uint16_t bf16_rn(float x) {
    uint16_t u; asm("cvt.rn.bf16.f32 %0,%1;" : "=h"(u) : "f"(x)); return u;
}
__device__ __forceinline__ float ex2f(float x) {
    float r; asm("ex2.approx.f32 %0,%1;" : "=f"(r) : "f"(x)); return r;
}
__device__ __forceinline__ uint32_t swz128(uint32_t o) { return o ^ ((o >> 3) & 0x70u); }
__device__ __forceinline__ uint32_t swz64(uint32_t o)  { return o ^ ((o >> 3) & 0x30u); }

__device__ __forceinline__ void cp16(uint32_t dst, const void* src) {
    asm volatile("cp.async.cg.shared.global [%0], [%1], 16;" :: "r"(dst), "l"(src) : "memory");
}
__device__ __forceinline__ void cp_commit() {
    asm volatile("cp.async.commit_group;" ::: "memory");
}
template <int N> __device__ __forceinline__ void cp_wait() {
    asm volatile("cp.async.wait_group %0;" :: "n"(N) : "memory");
}

__device__ __forceinline__ void ldsm4(uint32_t& r0, uint32_t& r1, uint32_t& r2, uint32_t& r3,
                                      uint32_t addr) {
    asm volatile("ldmatrix.sync.aligned.m8n8.x4.shared.b16 {%0,%1,%2,%3}, [%4];"
                 : "=r"(r0), "=r"(r1), "=r"(r2), "=r"(r3) : "r"(addr));
}
__device__ __forceinline__ void ldsm4t(uint32_t& r0, uint32_t& r1, uint32_t& r2, uint32_t& r3,
                                       uint32_t addr) {
    asm volatile("ldmatrix.sync.aligned.m8n8.x4.trans.shared.b16 {%0,%1,%2,%3}, [%4];"
                 : "=r"(r0), "=r"(r1), "=r"(r2), "=r"(r3) : "r"(addr));
}
__device__ __forceinline__ void mma_bf16(float* c, const uint32_t* a, uint32_t b0, uint32_t b1) {
    asm volatile(
        "mma.sync.aligned.m16n8k16.row.col.f32.bf16.bf16.f32 "
        "{%0,%1,%2,%3},{%4,%5,%6,%7},{%8,%9},{%0,%1,%2,%3};"
        : "+f"(c[0]), "+f"(c[1]), "+f"(c[2]), "+f"(c[3])
        : "r"(a[0]), "r"(a[1]), "r"(a[2]), "r"(a[3]), "r"(b0), "r"(b1));
}
__device__ __forceinline__ void mma_f16(float* c, const uint32_t* a, uint32_t b0, uint32_t b1) {
    asm volatile(
        "mma.sync.aligned.m16n8k16.row.col.f32.f16.f16.f32 "
        "{%0,%1,%2,%3},{%4,%5,%6,%7},{%8,%9},{%0,%1,%2,%3};"
        : "+f"(c[0]), "+f"(c[1]), "+f"(c[2]), "+f"(c[3])
        : "r"(a[0]), "r"(a[1]), "r"(a[2]), "r"(a[3]), "r"(b0), "r"(b1));
}

// ============================================================
// conversion kernels: fp32 -> bf16 hi/lo split
// ============================================================
__global__ __launch_bounds__(256) void conv_x_kernel(const float* __restrict__ x)
{
    size_t gid = (size_t)blockIdx.x * 256 + threadIdx.x;
    size_t i = gid * 4;
    float4 v = *(const float4*)(x + i);
    uint32_t bx = f2u(v.x), by = f2u(v.y), bz = f2u(v.z), bw = f2u(v.w);
    uint2 H, Lw;
    H.x = prmt_hi16(bx, by);
    H.y = prmt_hi16(bz, bw);
    Lw.x = cvt_bf16x2(v.x - __uint_as_float(bx & 0xffff0000u),
                      v.y - __uint_as_float(by & 0xffff0000u));
    Lw.y = cvt_bf16x2(v.z - __uint_as_float(bz & 0xffff0000u),
                      v.w - __uint_as_float(bw & 0xffff0000u));
    *(uint2*)(gx_hi + i) = H;
    *(uint2*)(gx_lo + i) = Lw;
}

__global__ __launch_bounds__(256) void conv_wT_kernel(const float* __restrict__ w,
                                                      int K, int N, int which)
{
    __shared__ float t[32][33];
    uint16_t* dh = which ? gwo_hi : gwi_hi;
    uint16_t* dl = which ? gwo_lo : gwi_lo;
    int n0 = blockIdx.x * 32, k0 = blockIdx.y * 32;
    int tx = threadIdx.x & 31, ty = threadIdx.x >> 5;
#pragma unroll
    for (int i = 0; i < 4; i++)
        t[ty + 8 * i][tx] = w[(size_t)(k0 + ty + 8 * i) * N + n0 + tx];
    __syncthreads();
#pragma unroll
    for (int i = 0; i < 4; i++) {
        int nn = ty + 8 * i;
        float v = t[tx][nn];
        uint32_t b = f2u(v);
        size_t idx = (size_t)(n0 + nn) * K + k0 + tx;
        dh[idx] = (uint16_t)(b >> 16);
        dl[idx] = bf16_rn(v - __uint_as_float(b & 0xffff0000u));
    }
}

// ============================================================
// GEMM bf16x3: CTA tile 128x128, 256 thr, warp tile 32x64,
// k-chunk 32, 3-stage cp.async pipeline, SW64 swizzle, 2 CTA/SM.
// MODE 0 epilogue -> q/k/v fp16 single (head-major).
// MODE 1 epilogue -> fp32 Cout.
// ============================================================
#define GSTAGE 32768u

template <int MODE>
__global__ __launch_bounds__(256, 2) void gemm_bf16_kernel(
    const float* __restrict__ bias, float* __restrict__ Cout)
{
    extern __shared__ char smp[];
    const uint32_t sbase = smem_u32(smp);
    int tid = threadIdx.x;
    int lane = tid & 31, w = tid >> 5;
    int wm = w >> 1, wn = w & 1;     // 4 x 2 warp grid, warp tile 32x64
    int bm = blockIdx.y, bn = blockIdx.x;

    const uint16_t* Ahi = (MODE == 0) ? gx_hi : gctx_hi;
    const uint16_t* Alo = (MODE == 0) ? gx_lo : gctx_lo;
    const uint16_t* Bhi = (MODE == 0) ? gwi_hi : gwo_hi;
    const uint16_t* Blo = (MODE == 0) ? gwi_lo : gwo_lo;

    int r = tid >> 1, g0 = (tid & 1) * 2;
    size_t aoff = (size_t)(bm * 128 + r) * HIDDEN;
    size_t boff = (size_t)(bn * 128 + r) * HIDDEN;

    float acc[2][8][4];
#pragma unroll
    for (int i = 0; i < 2; i++)
#pragma unroll
        for (int j = 0; j < 8; j++)
#pragma unroll
            for (int e = 0; e < 4; e++) acc[i][j][e] = 0.f;

#define ISSUE_CHUNK(kc, buf) do {                                               \
        uint32_t dst = sbase + (uint32_t)(buf) * GSTAGE;                         \
        const uint16_t* ah = Ahi + aoff + (kc) * 32;                             \
        const uint16_t* al = Alo + aoff + (kc) * 32;                             \
        const uint16_t* bh = Bhi + boff + (kc) * 32;                             \
        const uint16_t* bl = Blo + boff + (kc) * 32;                             \
        _Pragma("unroll")                                                        \
        for (int i = 0; i < 2; i++) {                                            \
            uint32_t so = swz64((uint32_t)r * 64u + (uint32_t)(g0 + i) * 16u);   \
            cp16(dst + so,           ah + (g0 + i) * 8);                         \
            cp16(dst + 8192u  + so,  al + (g0 + i) * 8);                         \
            cp16(dst + 16384u + so,  bh + (g0 + i) * 8);                         \
            cp16(dst + 24576u + so,  bl + (g0 + i) * 8);                         \
        }                                                                        \
        cp_commit();                                                             \
    } while (0)

    ISSUE_CHUNK(0, 0);
    ISSUE_CHUNK(1, 1);

    const int NK = HIDDEN / 32;   // 16 chunks
    int rb = 0;
    for (int kc = 0; kc < NK; kc++) {
        if (kc + 2 < NK) {
            int wb = rb + 2; if (wb >= 3) wb -= 3;
            ISSUE_CHUNK(kc + 2, wb);
            cp_wait<2>();
        } else if (kc + 1 < NK) {
            cp_wait<1>();
        } else {
            cp_wait<0>();
        }
        __syncthreads();

        uint32_t abase = sbase + (uint32_t)rb * GSTAGE;
        uint32_t bbase = abase + 16384u;
#pragma unroll
        for (int ks = 0; ks < 2; ks++) {
            uint32_t ah[2][4], al[2][4];
#pragma unroll
            for (int mi = 0; mi < 2; mi++) {
                uint32_t off = swz64((uint32_t)(wm * 32 + mi * 16 + (lane & 15)) * 64u
                                     + (uint32_t)(ks * 32 + ((lane & 16) ? 16 : 0)));
                ldsm4(ah[mi][0], ah[mi][1], ah[mi][2], ah[mi][3], abase + off);
                ldsm4(al[mi][0], al[mi][1], al[mi][2], al[mi][3], abase + 8192u + off);
            }
#pragma unroll
            for (int np = 0; np < 4; np++) {
                uint32_t boffs = swz64((uint32_t)(wn * 64 + np * 16 + (lane & 7)
                                                  + ((lane & 16) ? 8 : 0)) * 64u
                                       + (uint32_t)(ks * 32 + ((lane & 8) ? 16 : 0)));
                uint32_t bh0, bh1, bh2, bh3, bl0, bl1, bl2, bl3;
                ldsm4(bh0, bh1, bh2, bh3, bbase + boffs);
                ldsm4(bl0, bl1, bl2, bl3, bbase + 8192u + boffs);
#pragma unroll
                for (int mi = 0; mi < 2; mi++) {
                    mma_bf16(acc[mi][2 * np],     ah[mi], bh0, bh1);
                    mma_bf16(acc[mi][2 * np + 1], ah[mi], bh2, bh3);
                }
#pragma unroll
                for (int mi = 0; mi < 2; mi++) {
                    mma_bf16(acc[mi][2 * np],     ah[mi], bl0, bl1);
                    mma_bf16(acc[mi][2 * np + 1], ah[mi], bl2, bl3);
                }
#pragma unroll
                for (int mi = 0; mi < 2; mi++) {
                    mma_bf16(acc[mi][2 * np],     al[mi], bh0, bh1);
                    mma_bf16(acc[mi][2 * np + 1], al[mi], bh2, bh3);
                }
            }
        }
        __syncthreads();
        rb = rb + 1; if (rb == 3) rb = 0;
    }
#undef ISSUE_CHUNK

    // ---- epilogue ----
#pragma unroll
    for (int mi = 0; mi < 2; mi++) {
        int r0 = bm * 128 + wm * 32 + mi * 16 + (lane >> 2);
#pragma unroll
        for (int nj = 0; nj < 8; nj++) {
            int c0 = bn * 128 + wn * 64 + nj * 8 + 2 * (lane & 3);
            float bb0 = __ldg(bias + c0), bb1 = __ldg(bias + c0 + 1);
            float v0 = acc[mi][nj][0] + bb0, v1 = acc[mi][nj][1] + bb1;
            float v2 = acc[mi][nj][2] + bb0, v3 = acc[mi][nj][3] + bb1;
            if (MODE == 0) {
                int which = c0 >> 9, h = (c0 >> 6) & 7, d = c0 & 63;
                uint16_t* dq = (which == 0) ? gq_f16 : (which == 1) ? gk_f16 : gv_f16;
                int b = r0 >> 12;
                size_t base0 = ((size_t)((b * 8 + h) * L_ + (r0 & 4095))) * 64 + d;
                size_t base1 = base0 + 8 * 64;
                *(uint32_t*)(dq + base0) = cvt_f16x2(v0, v1);
                *(uint32_t*)(dq + base1) = cvt_f16x2(v2, v3);
            } else {
                *(float2*)(Cout + (size_t)r0 * HIDDEN + c0) = make_float2(v0, v1);
                *(float2*)(Cout + (size_t)(r0 + 8) * HIDDEN + c0) = make_float2(v2, v3);
            }
        }
    }
}

// ============================================================
// Attention (single-pass fp16): Q 16KB; K/V double buffer
// (2 x 16KB: K 8KB + V 8KB). Total 48KB. 2 CTAs/SM.
// ============================================================
#define SQ   0u
#define SKV0 16384u
#define ATTN_SMEM 49152

__global__ __launch_bounds__(256, 2) void attn_mma_kernel()
{
    extern __shared__ char smp[];
    const uint32_t sbase = smem_u32(smp);
    int tid = threadIdx.x;
    int w = tid >> 5, lane = tid & 31;

    int bh = blockIdx.x;                            // b*8 + h
    int qt = (int)gridDim.y - 1 - (int)blockIdx.y;  // heavy tiles first
    int nkt = 2 * qt + 2;                           // 64-key tiles

    int ct = tid & 127;
    int rr = ct >> 1, g0 = (ct & 1) * 4;
    const uint16_t* srckv = (tid < 128) ? gk_f16 : gv_f16;
    uint32_t dsel = (tid < 128) ? 0u : 8192u;

#define ISSUE_KV(kt, buf) do {                                                   \
        uint32_t dst = sbase + SKV0 + (uint32_t)(buf) * 16384u + dsel;           \
        const uint16_t* sp = srckv + ((size_t)bh * L_ + (size_t)(kt) * 64 + rr) * 64; \
        _Pragma("unroll")                                                        \
        for (int i = 0; i < 4; i++) {                                            \
            uint32_t so = swz128((uint32_t)rr * 128u + (uint32_t)(g0 + i) * 16u);\
            cp16(dst + so, sp + (g0 + i) * 8);                                   \
        }                                                                        \
        cp_commit();                                                             \
    } while (0)

    // Prologue: Q tile copy + first K/V issue
    {
        const uint4* q4 = (const uint4*)(gq_f16 + ((size_t)bh * L_ + (size_t)qt * 128 + (tid >> 1)) * 64);
        int qg0 = (tid & 1) * 4;
#pragma unroll
        for (int i = 0; i < 4; i++) {
            uint32_t so = swz128((uint32_t)(tid >> 1) * 128u + (uint32_t)(qg0 + i) * 16u);
            *(uint4*)(smp + SQ + so) = q4[qg0 + i];
        }
    }
    ISSUE_KV(0, 0);
    __syncthreads();

    int arow = 16 * w + (lane & 15);
    uint32_t qf[4][4];   // fp16 Q A-fragments, resident whole kernel
    {
#pragma unroll
        for (int ks = 0; ks < 4; ks++) {
            uint32_t off = swz128((uint32_t)arow * 128u
                                  + (uint32_t)(ks * 32 + ((lane & 16) ? 16 : 0)));
            ldsm4(qf[ks][0], qf[ks][1], qf[ks][2], qf[ks][3], sbase + SQ + off);
        }
    }

    float oc[8][4];
#pragma unroll
    for (int n = 0; n < 8; n++)
#pragma unroll
        for (int j = 0; j < 4; j++) oc[n][j] = 0.f;
    float lsum0 = 0.f, lsum1 = 0.f;

    const float Cc = 0.18033688011112042f;  // (1/8) * log2(e)
    int row0 = qt * 128 + 16 * w + (lane >> 2);
    int row1 = row0 + 8;

    for (int kt = 0; kt < nkt; ++kt) {
        if (kt + 1 < nkt) {
            ISSUE_KV(kt + 1, (kt + 1) & 1);
            cp_wait<1>();
        } else {
            cp_wait<0>();
        }
        __syncthreads();

        uint32_t kvb = sbase + SKV0 + (uint32_t)(kt & 1) * 16384u;

        // ---- S = Q K^T : single-pass fp16 ----
        float sc[8][4];
#pragma unroll
        for (int n = 0; n < 8; n++)
#pragma unroll
            for (int j = 0; j < 4; j++) sc[n][j] = 0.f;

#pragma unroll
        for (int ks = 0; ks < 4; ks++) {
#pragma unroll
            for (int npp = 0; npp < 2; npp++) {
                int key0 = (2 * npp) * 16 + (lane & 7) + ((lane & 16) ? 8 : 0);
                uint32_t col = (uint32_t)(ks * 32 + ((lane & 8) ? 16 : 0));
                uint32_t off0 = swz128((uint32_t)key0 * 128u + col);
                uint32_t off1 = swz128((uint32_t)(key0 + 16) * 128u + col);
                uint32_t b00, b01, b02, b03, b10, b11, b12, b13;
                ldsm4(b00, b01, b02, b03, kvb + off0);
                ldsm4(b10, b11, b12, b13, kvb + off1);
                mma_f16(sc[4 * npp + 0], qf[ks], b00, b01);
                mma_f16(sc[4 * npp + 1], qf[ks], b02, b03);
                mma_f16(sc[4 * npp + 2], qf[ks], b10, b11);
                mma_f16(sc[4 * npp + 3], qf[ks], b12, b13);
            }
        }

        // ---- softmax (unnormalized) ----
        bool edge = (kt == 0) || (kt >= 2 * qt);
        int colb = kt * 64 + 2 * (lane & 3);
#pragma unroll
        for (int n = 0; n < 8; n++) {
            float e0 = ex2f(sc[n][0] * Cc);
            float e1 = ex2f(sc[n][1] * Cc);
            float e2 = ex2f(sc[n][2] * Cc);
            float e3 = ex2f(sc[n][3] * Cc);
            if (edge) {
                int c0 = colb + 8 * n, c1 = c0 + 1;
                bool k00 = (c0 <= row0) && (c0 >= PREFIX || row0 < PREFIX);
                bool k01 = (c1 <= row0) && (c1 >= PREFIX || row0 < PREFIX);
                bool k10 = (c0 <= row1) && (c0 >= PREFIX || row1 < PREFIX);
                bool k11 = (c1 <= row1) && (c1 >= PREFIX || row1 < PREFIX);
                e0 = k00 ? e0 : 0.f;
                e1 = k01 ? e1 : 0.f;
                e2 = k10 ? e2 : 0.f;
                e3 = k11 ? e3 : 0.f;
            }
            sc[n][0] = e0; sc[n][1] = e1; sc[n][2] = e2; sc[n][3] = e3;
            lsum0 += e0 + e1;
            lsum1 += e2 + e3;
        }

        // ---- O += P V : single-pass fp16 ----
#pragma unroll
        for (int t = 0; t < 4; t++) {
            uint32_t pf[4];
            pf[0] = cvt_f16x2(sc[2 * t][0],     sc[2 * t][1]);
            pf[1] = cvt_f16x2(sc[2 * t][2],     sc[2 * t][3]);
            pf[2] = cvt_f16x2(sc[2 * t + 1][0], sc[2 * t + 1][1]);
            pf[3] = cvt_f16x2(sc[2 * t + 1][2], sc[2 * t + 1][3]);
            int key = t * 16 + (lane & 7) + ((lane & 8) ? 8 : 0);
#pragma unroll
            for (int dpp = 0; dpp < 2; dpp++) {
                uint32_t col0 = (uint32_t)((2 * dpp) * 32 + ((lane & 16) ? 16 : 0));
                uint32_t off0 = swz128((uint32_t)key * 128u + col0);
                uint32_t off1 = swz128((uint32_t)key * 128u + col0 + 32u);
                uint32_t v00, v01, v02, v03, v10, v11, v12, v13;
                ldsm4t(v00, v01, v02, v03, kvb + 8192u + off0);
                ldsm4t(v10, v11, v12, v13, kvb + 8192u + off1);
                mma_f16(oc[4 * dpp + 0], pf, v00, v01);
                mma_f16(oc[4 * dpp + 1], pf, v02, v03);
                mma_f16(oc[4 * dpp + 2], pf, v10, v11);
                mma_f16(oc[4 * dpp + 3], pf, v12, v13);
            }
        }
        __syncthreads();
    }
#undef ISSUE_KV

    // lane reduction of lsum
    lsum0 += __shfl_xor_sync(0xffffffffu, lsum0, 1);
    lsum0 += __shfl_xor_sync(0xffffffffu, lsum0, 2);
    lsum1 += __shfl_xor_sync(0xffffffffu, lsum1, 1);
    lsum1 += __shfl_xor_sync(0xffffffffu, lsum1, 2);
    float inv0 = 1.f / lsum0, inv1 = 1.f / lsum1;

    // store ctx as bf16 hi/lo (gemm1 input precision)
    int b = bh >> 3, h = bh & 7;
    size_t r0base = (size_t)(b * L_ + row0) * HIDDEN + h * 64;
    size_t r1base = (size_t)(b * L_ + row1) * HIDDEN + h * 64;
#pragma unroll
    for (int n = 0; n < 8; n++) {
        int d = 8 * n + 2 * (lane & 3);
        float v0 = oc[n][0] * inv0, v1 = oc[n][1] * inv0;
        float v2 = oc[n][2] * inv1, v3 = oc[n][3] * inv1;
        uint32_t u0 = f2u(v0), u1 = f2u(v1), u2 = f2u(v2), u3 = f2u(v3);
        *(uint32_t*)(gctx_hi + r0base + d) = prmt_hi16(u0, u1);
        *(uint32_t*)(gctx_lo + r0base + d) =
            cvt_bf16x2(v0 - __uint_as_float(u0 & 0xffff0000u),
                       v1 - __uint_as_float(u1 & 0xffff0000u));
        *(uint32_t*)(gctx_hi + r1base + d) = prmt_hi16(u2, u3);
        *(uint32_t*)(gctx_lo + r1base + d) =
            cvt_bf16x2(v2 - __uint_as_float(u2 & 0xffff0000u),
                       v3 - __uint_as_float(u3 & 0xffff0000u));
    }
}

// ============================================================
extern "C" void kernel_launch(void* const* d_in, const int* in_sizes, int n_in,
                              void* d_out, int out_size)
{
    const float* x     = (const float*)d_in[0];
    const float* w_in  = (const float*)d_in[1];
    const float* b_in  = (const float*)d_in[2];
    const float* w_out = (const float*)d_in[3];
    const float* b_out = (const float*)d_in[4];
    float* out = (float*)d_out;

    conv_x_kernel<<<(M_ROWS * HIDDEN / 4) / 256, 256>>>(x);
    conv_wT_kernel<<<dim3(3 * HIDDEN / 32, HIDDEN / 32), 256>>>(w_in, HIDDEN, 3 * HIDDEN, 0);
    conv_wT_kernel<<<dim3(HIDDEN / 32, HIDDEN / 32), 256>>>(w_out, HIDDEN, HIDDEN, 1);

    cudaFuncSetAttribute(gemm_bf16_kernel<0>,
                         cudaFuncAttributeMaxDynamicSharedMemorySize, 3 * GSTAGE);
    gemm_bf16_kernel<0><<<dim3(12, 64), 256, 3 * GSTAGE>>>(b_in, nullptr);

    cudaFuncSetAttribute(attn_mma_kernel,
                         cudaFuncAttributeMaxDynamicSharedMemorySize, ATTN_SMEM);
    attn_mma_kernel<<<dim3(16, 32), 256, ATTN_SMEM>>>();

    cudaFuncSetAttribute(gemm_bf16_kernel<1>,
                         cudaFuncAttributeMaxDynamicSharedMemorySize, 3 * GSTAGE);
    gemm_bf16_kernel<1><<<dim3(4, 64), 256, 3 * GSTAGE>>>(b_out, out);
}

// round 12
// speedup vs baseline: 2.3895x; 1.4290x over previous
#include <cuda_runtime.h>
#include <cstdint>

typedef unsigned long long ull;

#define B_      2
#define L_      4096
#define HIDDEN  512
#define HEADS   8
#define HD      64
#define PREFIX  1
#define M_ROWS  (B_ * L_)        // 8192

// ---- fp16 storage (allocation-free: __device__ globals) ----
__device__ __align__(16) uint16_t gx_f16[M_ROWS * HIDDEN];
__device__ __align__(16) uint16_t gwi_f16[3 * HIDDEN * HIDDEN];
__device__ __align__(16) uint16_t gwo_f16[HIDDEN * HIDDEN];
__device__ __align__(16) uint16_t gq_f16[M_ROWS * HIDDEN];
__device__ __align__(16) uint16_t gk_f16[M_ROWS * HIDDEN];
__device__ __align__(16) uint16_t gv_f16[M_ROWS * HIDDEN];
__device__ __align__(16) uint16_t gctx_f16[M_ROWS * HIDDEN];

// ============================================================
// helpers
// ============================================================
__device__ __forceinline__ uint32_t smem_u32(const void* p) {
    uint32_t a;
    asm("{ .reg .u64 t; cvta.to.shared.u64 t, %1; cvt.u32.u64 %0, t; }" : "=r"(a) : "l"(p));
    return a;
}
// pack {lo, hi} floats into f16x2 (first arg -> low half)
__device__ __forceinline__ uint32_t cvt_f16x2(float lo, float hi) {
    uint32_t r; asm("cvt.rn.f16x2.f32 %0,%1,%2;" : "=r"(r) : "f"(hi), "f"(lo)); return r;
}
__device__ __forceinline__ float ex2f(float x) {
    float r; asm("ex2.approx.f32 %0,%1;" : "=f"(r) : "f"(x)); return r;
}
__device__ __forceinline__ uint32_t swz128(uint32_t o) { return o ^ ((o >> 3) & 0x70u); }
__device__ __forceinline__ uint32_t swz64(uint32_t o)  { return o ^ ((o >> 3) & 0x30u); }

__device__ __forceinline__ void cp16(uint32_t dst, const void* src) {
    asm volatile("cp.async.cg.shared.global [%0], [%1], 16;" :: "r"(dst), "l"(src) : "memory");
}
__device__ __forceinline__ void cp_commit() {
    asm volatile("cp.async.commit_group;" ::: "memory");
}
template <int N> __device__ __forceinline__ void cp_wait() {
    asm volatile("cp.async.wait_group %0;" :: "n"(N) : "memory");
}

__device__ __forceinline__ void ldsm4(uint32_t& r0, uint32_t& r1, uint32_t& r2, uint32_t& r3,
                                      uint32_t addr) {
    asm volatile("ldmatrix.sync.aligned.m8n8.x4.shared.b16 {%0,%1,%2,%3}, [%4];"
                 : "=r"(r0), "=r"(r1), "=r"(r2), "=r"(r3) : "r"(addr));
}
__device__ __forceinline__ void ldsm4t(uint32_t& r0, uint32_t& r1, uint32_t& r2, uint32_t& r3,
                                       uint32_t addr) {
    asm volatile("ldmatrix.sync.aligned.m8n8.x4.trans.shared.b16 {%0,%1,%2,%3}, [%4];"
                 : "=r"(r0), "=r"(r1), "=r"(r2), "=r"(r3) : "r"(addr));
}
__device__ __forceinline__ void mma_f16(float* c, const uint32_t* a, uint32_t b0, uint32_t b1) {
    asm volatile(
        "mma.sync.aligned.m16n8k16.row.col.f32.f16.f16.f32 "
        "{%0,%1,%2,%3},{%4,%5,%6,%7},{%8,%9},{%0,%1,%2,%3};"
        : "+f"(c[0]), "+f"(c[1]), "+f"(c[2]), "+f"(c[3])
        : "r"(a[0]), "r"(a[1]), "r"(a[2]), "r"(a[3]), "r"(b0), "r"(b1));
}

// ============================================================
// conversion kernels: fp32 -> fp16
// ============================================================
__global__ __launch_bounds__(256) void conv_x_kernel(const float* __restrict__ x)
{
    size_t gid = (size_t)blockIdx.x * 256 + threadIdx.x;
    size_t i = gid * 4;
    float4 v = *(const float4*)(x + i);
    uint2 H;
    H.x = cvt_f16x2(v.x, v.y);
    H.y = cvt_f16x2(v.z, v.w);
    *(uint2*)(gx_f16 + i) = H;
}

// transpose+convert: w [K, N] fp32 -> wT [N, K] fp16. which: 0=w_in, 1=w_out
__global__ __launch_bounds__(256) void conv_wT_kernel(const float* __restrict__ w,
                                                      int K, int N, int which)
{
    __shared__ float t[32][33];
    uint16_t* dst = which ? gwo_f16 : gwi_f16;
    int n0 = blockIdx.x * 32, k0 = blockIdx.y * 32;
    int tx = threadIdx.x & 31, ty = threadIdx.x >> 5;
#pragma unroll
    for (int i = 0; i < 4; i++)
        t[ty + 8 * i][tx] = w[(size_t)(k0 + ty + 8 * i) * N + n0 + tx];
    __syncthreads();
#pragma unroll
    for (int i = 0; i < 4; i++) {
        int nn = ty + 8 * i;
        float v = t[tx][nn];
        uint16_t h;
        asm("cvt.rn.f16.f32 %0,%1;" : "=h"(h) : "f"(v));
        dst[(size_t)(n0 + nn) * K + k0 + tx] = h;
    }
}

// ============================================================
// GEMM single-pass fp16: CTA tile 128x128, 256 thr, warp tile 32x64,
// k-chunk 32, 3-stage cp.async, SW64 swizzle, 2 CTA/SM.
// Stage (16KB): {A 0, B 8K}.
// MODE 0: A=gx, B=gwi; epilogue -> q/k/v fp16 head-major.
// MODE 1: A=gctx, B=gwo; epilogue -> fp32 Cout.
// ============================================================
#define GSTAGE 16384u

template <int MODE>
__global__ __launch_bounds__(256, 2) void gemm_f16_kernel(
    const float* __restrict__ bias, float* __restrict__ Cout)
{
    extern __shared__ char smp[];
    const uint32_t sbase = smem_u32(smp);
    int tid = threadIdx.x;
    int lane = tid & 31, w = tid >> 5;
    int wm = w >> 1, wn = w & 1;     // 4 x 2 warp grid, warp tile 32x64
    int bm = blockIdx.y, bn = blockIdx.x;

    const uint16_t* A = (MODE == 0) ? gx_f16 : gctx_f16;
    const uint16_t* Bw = (MODE == 0) ? gwi_f16 : gwo_f16;

    // loaders: 2 thr/row (64B row), 2 16B-groups per thread
    int r = tid >> 1, g0 = (tid & 1) * 2;
    size_t aoff = (size_t)(bm * 128 + r) * HIDDEN;
    size_t boff = (size_t)(bn * 128 + r) * HIDDEN;

    float acc[2][8][4];
#pragma unroll
    for (int i = 0; i < 2; i++)
#pragma unroll
        for (int j = 0; j < 8; j++)
#pragma unroll
            for (int e = 0; e < 4; e++) acc[i][j][e] = 0.f;

#define ISSUE_CHUNK(kc, buf) do {                                               \
        uint32_t dst = sbase + (uint32_t)(buf) * GSTAGE;                         \
        const uint16_t* ap = A  + aoff + (kc) * 32;                              \
        const uint16_t* bp = Bw + boff + (kc) * 32;                              \
        _Pragma("unroll")                                                        \
        for (int i = 0; i < 2; i++) {                                            \
            uint32_t so = swz64((uint32_t)r * 64u + (uint32_t)(g0 + i) * 16u);   \
            cp16(dst + so,          ap + (g0 + i) * 8);                          \
            cp16(dst + 8192u + so,  bp + (g0 + i) * 8);                          \
        }                                                                        \
        cp_commit();                                                             \
    } while (0)

    ISSUE_CHUNK(0, 0);
    ISSUE_CHUNK(1, 1);

    const int NK = HIDDEN / 32;   // 16 chunks
    int rb = 0;
    for (int kc = 0; kc < NK; kc++) {
        if (kc + 2 < NK) {
            int wb = rb + 2; if (wb >= 3) wb -= 3;
            ISSUE_CHUNK(kc + 2, wb);
            cp_wait<2>();
        } else if (kc + 1 < NK) {
            cp_wait<1>();
        } else {
            cp_wait<0>();
        }
        __syncthreads();

        uint32_t abase = sbase + (uint32_t)rb * GSTAGE;
        uint32_t bbase = abase + 8192u;
#pragma unroll
        for (int ks = 0; ks < 2; ks++) {
            uint32_t ah[2][4];
#pragma unroll
            for (int mi = 0; mi < 2; mi++) {
                uint32_t off = swz64((uint32_t)(wm * 32 + mi * 16 + (lane & 15)) * 64u
                                     + (uint32_t)(ks * 32 + ((lane & 16) ? 16 : 0)));
                ldsm4(ah[mi][0], ah[mi][1], ah[mi][2], ah[mi][3], abase + off);
            }
#pragma unroll
            for (int np = 0; np < 4; np++) {
                uint32_t boffs = swz64((uint32_t)(wn * 64 + np * 16 + (lane & 7)
                                                  + ((lane & 16) ? 8 : 0)) * 64u
                                       + (uint32_t)(ks * 32 + ((lane & 8) ? 16 : 0)));
                uint32_t b0, b1, b2, b3;
                ldsm4(b0, b1, b2, b3, bbase + boffs);
#pragma unroll
                for (int mi = 0; mi < 2; mi++) {
                    mma_f16(acc[mi][2 * np],     ah[mi], b0, b1);
                    mma_f16(acc[mi][2 * np + 1], ah[mi], b2, b3);
                }
            }
        }
        __syncthreads();
        rb = rb + 1; if (rb == 3) rb = 0;
    }
#undef ISSUE_CHUNK

    // ---- epilogue ----
#pragma unroll
    for (int mi = 0; mi < 2; mi++) {
        int r0 = bm * 128 + wm * 32 + mi * 16 + (lane >> 2);
#pragma unroll
        for (int nj = 0; nj < 8; nj++) {
            int c0 = bn * 128 + wn * 64 + nj * 8 + 2 * (lane & 3);
            float bb0 = __ldg(bias + c0), bb1 = __ldg(bias + c0 + 1);
            float v0 = acc[mi][nj][0] + bb0, v1 = acc[mi][nj][1] + bb1;
            float v2 = acc[mi][nj][2] + bb0, v3 = acc[mi][nj][3] + bb1;
            if (MODE == 0) {
                int which = c0 >> 9, h = (c0 >> 6) & 7, d = c0 & 63;
                uint16_t* dq = (which == 0) ? gq_f16 : (which == 1) ? gk_f16 : gv_f16;
                int b = r0 >> 12;
                size_t base0 = ((size_t)((b * 8 + h) * L_ + (r0 & 4095))) * 64 + d;
                size_t base1 = base0 + 8 * 64;
                *(uint32_t*)(dq + base0) = cvt_f16x2(v0, v1);
                *(uint32_t*)(dq + base1) = cvt_f16x2(v2, v3);
            } else {
                *(float2*)(Cout + (size_t)r0 * HIDDEN + c0) = make_float2(v0, v1);
                *(float2*)(Cout + (size_t)(r0 + 8) * HIDDEN + c0) = make_float2(v2, v3);
            }
        }
    }
}

// ============================================================
// Attention (single-pass fp16): Q 16KB; K/V double buffer
// (2 x 16KB: K 8KB + V 8KB). Total 48KB. 2 CTAs/SM.
// ============================================================
#define SQ   0u
#define SKV0 16384u
#define ATTN_SMEM 49152

__global__ __launch_bounds__(256, 2) void attn_mma_kernel()
{
    extern __shared__ char smp[];
    const uint32_t sbase = smem_u32(smp);
    int tid = threadIdx.x;
    int w = tid >> 5, lane = tid & 31;

    int bh = blockIdx.x;                            // b*8 + h
    int qt = (int)gridDim.y - 1 - (int)blockIdx.y;  // heavy tiles first
    int nkt = 2 * qt + 2;                           // 64-key tiles

    int ct = tid & 127;
    int rr = ct >> 1, g0 = (ct & 1) * 4;
    const uint16_t* srckv = (tid < 128) ? gk_f16 : gv_f16;
    uint32_t dsel = (tid < 128) ? 0u : 8192u;

#define ISSUE_KV(kt, buf) do {                                                   \
        uint32_t dst = sbase + SKV0 + (uint32_t)(buf) * 16384u + dsel;           \
        const uint16_t* sp = srckv + ((size_t)bh * L_ + (size_t)(kt) * 64 + rr) * 64; \
        _Pragma("unroll")                                                        \
        for (int i = 0; i < 4; i++) {                                            \
            uint32_t so = swz128((uint32_t)rr * 128u + (uint32_t)(g0 + i) * 16u);\
            cp16(dst + so, sp + (g0 + i) * 8);                                   \
        }                                                                        \
        cp_commit();                                                             \
    } while (0)

    // Prologue: Q tile copy + first K/V issue
    {
        const uint4* q4 = (const uint4*)(gq_f16 + ((size_t)bh * L_ + (size_t)qt * 128 + (tid >> 1)) * 64);
        int qg0 = (tid & 1) * 4;
#pragma unroll
        for (int i = 0; i < 4; i++) {
            uint32_t so = swz128((uint32_t)(tid >> 1) * 128u + (uint32_t)(qg0 + i) * 16u);
            *(uint4*)(smp + SQ + so) = q4[qg0 + i];
        }
    }
    ISSUE_KV(0, 0);
    __syncthreads();

    int arow = 16 * w + (lane & 15);
    uint32_t qf[4][4];   // fp16 Q A-fragments, resident whole kernel
    {
#pragma unroll
        for (int ks = 0; ks < 4; ks++) {
            uint32_t off = swz128((uint32_t)arow * 128u
                                  + (uint32_t)(ks * 32 + ((lane & 16) ? 16 : 0)));
            ldsm4(qf[ks][0], qf[ks][1], qf[ks][2], qf[ks][3], sbase + SQ + off);
        }
    }

    float oc[8][4];
#pragma unroll
    for (int n = 0; n < 8; n++)
#pragma unroll
        for (int j = 0; j < 4; j++) oc[n][j] = 0.f;
    float lsum0 = 0.f, lsum1 = 0.f;

    const float Cc = 0.18033688011112042f;  // (1/8) * log2(e)
    int row0 = qt * 128 + 16 * w + (lane >> 2);
    int row1 = row0 + 8;

    for (int kt = 0; kt < nkt; ++kt) {
        if (kt + 1 < nkt) {
            ISSUE_KV(kt + 1, (kt + 1) & 1);
            cp_wait<1>();
        } else {
            cp_wait<0>();
        }
        __syncthreads();

        uint32_t kvb = sbase + SKV0 + (uint32_t)(kt & 1) * 16384u;

        // ---- S = Q K^T : single-pass fp16 ----
        float sc[8][4];
#pragma unroll
        for (int n = 0; n < 8; n++)
#pragma unroll
            for (int j = 0; j < 4; j++) sc[n][j] = 0.f;

#pragma unroll
        for (int ks = 0; ks < 4; ks++) {
#pragma unroll
            for (int npp = 0; npp < 2; npp++) {
                int key0 = (2 * npp) * 16 + (lane & 7) + ((lane & 16) ? 8 : 0);
                uint32_t col = (uint32_t)(ks * 32 + ((lane & 8) ? 16 : 0));
                uint32_t off0 = swz128((uint32_t)key0 * 128u + col);
                uint32_t off1 = swz128((uint32_t)(key0 + 16) * 128u + col);
                uint32_t b00, b01, b02, b03, b10, b11, b12, b13;
                ldsm4(b00, b01, b02, b03, kvb + off0);
                ldsm4(b10, b11, b12, b13, kvb + off1);
                mma_f16(sc[4 * npp + 0], qf[ks], b00, b01);
                mma_f16(sc[4 * npp + 1], qf[ks], b02, b03);
                mma_f16(sc[4 * npp + 2], qf[ks], b10, b11);
                mma_f16(sc[4 * npp + 3], qf[ks], b12, b13);
            }
        }

        // ---- softmax (unnormalized) ----
        bool edge = (kt == 0) || (kt >= 2 * qt);
        int colb = kt * 64 + 2 * (lane & 3);
#pragma unroll
        for (int n = 0; n < 8; n++) {
            float e0 = ex2f(sc[n][0] * Cc);
            float e1 = ex2f(sc[n][1] * Cc);
            float e2 = ex2f(sc[n][2] * Cc);
            float e3 = ex2f(sc[n][3] * Cc);
            if (edge) {
                int c0 = colb + 8 * n, c1 = c0 + 1;
                bool k00 = (c0 <= row0) && (c0 >= PREFIX || row0 < PREFIX);
                bool k01 = (c1 <= row0) && (c1 >= PREFIX || row0 < PREFIX);
                bool k10 = (c0 <= row1) && (c0 >= PREFIX || row1 < PREFIX);
                bool k11 = (c1 <= row1) && (c1 >= PREFIX || row1 < PREFIX);
                e0 = k00 ? e0 : 0.f;
                e1 = k01 ? e1 : 0.f;
                e2 = k10 ? e2 : 0.f;
                e3 = k11 ? e3 : 0.f;
            }
            sc[n][0] = e0; sc[n][1] = e1; sc[n][2] = e2; sc[n][3] = e3;
            lsum0 += e0 + e1;
            lsum1 += e2 + e3;
        }

        // ---- O += P V : single-pass fp16 ----
#pragma unroll
        for (int t = 0; t < 4; t++) {
            uint32_t pf[4];
            pf[0] = cvt_f16x2(sc[2 * t][0],     sc[2 * t][1]);
            pf[1] = cvt_f16x2(sc[2 * t][2],     sc[2 * t][3]);
            pf[2] = cvt_f16x2(sc[2 * t + 1][0], sc[2 * t + 1][1]);
            pf[3] = cvt_f16x2(sc[2 * t + 1][2], sc[2 * t + 1][3]);
            int key = t * 16 + (lane & 7) + ((lane & 8) ? 8 : 0);
#pragma unroll
            for (int dpp = 0; dpp < 2; dpp++) {
                uint32_t col0 = (uint32_t)((2 * dpp) * 32 + ((lane & 16) ? 16 : 0));
                uint32_t off0 = swz128((uint32_t)key * 128u + col0);
                uint32_t off1 = swz128((uint32_t)key * 128u + col0 + 32u);
                uint32_t v00, v01, v02, v03, v10, v11, v12, v13;
                ldsm4t(v00, v01, v02, v03, kvb + 8192u + off0);
                ldsm4t(v10, v11, v12, v13, kvb + 8192u + off1);
                mma_f16(oc[4 * dpp + 0], pf, v00, v01);
                mma_f16(oc[4 * dpp + 1], pf, v02, v03);
                mma_f16(oc[4 * dpp + 2], pf, v10, v11);
                mma_f16(oc[4 * dpp + 3], pf, v12, v13);
            }
        }
        __syncthreads();
    }
#undef ISSUE_KV

    // lane reduction of lsum
    lsum0 += __shfl_xor_sync(0xffffffffu, lsum0, 1);
    lsum0 += __shfl_xor_sync(0xffffffffu, lsum0, 2);
    lsum1 += __shfl_xor_sync(0xffffffffu, lsum1, 1);
    lsum1 += __shfl_xor_sync(0xffffffffu, lsum1, 2);
    float inv0 = 1.f / lsum0, inv1 = 1.f / lsum1;

    // store ctx as fp16 (gemm1 input)
    int b = bh >> 3, h = bh & 7;
    size_t r0base = (size_t)(b * L_ + row0) * HIDDEN + h * 64;
    size_t r1base = (size_t)(b * L_ + row1) * HIDDEN + h * 64;
#pragma unroll
    for (int n = 0; n < 8; n++) {
        int d = 8 * n + 2 * (lane & 3);
        *(uint32_t*)(gctx_f16 + r0base + d) = cvt_f16x2(oc[n][0] * inv0, oc[n][1] * inv0);
        *(uint32_t*)(gctx_f16 + r1base + d) = cvt_f16x2(oc[n][2] * inv1, oc[n][3] * inv1);
    }
}

// ============================================================
extern "C" void kernel_launch(void* const* d_in, const int* in_sizes, int n_in,
                              void* d_out, int out_size)
{
    const float* x     = (const float*)d_in[0];
    const float* w_in  = (const float*)d_in[1];
    const float* b_in  = (const float*)d_in[2];
    const float* w_out = (const float*)d_in[3];
    const float* b_out = (const float*)d_in[4];
    float* out = (float*)d_out;

    conv_x_kernel<<<(M_ROWS * HIDDEN / 4) / 256, 256>>>(x);
    conv_wT_kernel<<<dim3(3 * HIDDEN / 32, HIDDEN / 32), 256>>>(w_in, HIDDEN, 3 * HIDDEN, 0);
    conv_wT_kernel<<<dim3(HIDDEN / 32, HIDDEN / 32), 256>>>(w_out, HIDDEN, HIDDEN, 1);

    cudaFuncSetAttribute(gemm_f16_kernel<0>,
                         cudaFuncAttributeMaxDynamicSharedMemorySize, 3 * GSTAGE);
    gemm_f16_kernel<0><<<dim3(12, 64), 256, 3 * GSTAGE>>>(b_in, nullptr);

    cudaFuncSetAttribute(attn_mma_kernel,
                         cudaFuncAttributeMaxDynamicSharedMemorySize, ATTN_SMEM);
    attn_mma_kernel<<<dim3(16, 32), 256, ATTN_SMEM>>>();

    cudaFuncSetAttribute(gemm_f16_kernel<1>,
                         cudaFuncAttributeMaxDynamicSharedMemorySize, 3 * GSTAGE);
    gemm_f16_kernel<1><<<dim3(4, 64), 256, 3 * GSTAGE>>>(b_out, out);
}